// round 1
// baseline (speedup 1.0000x reference)
#include <cuda_runtime.h>

// ---------------- problem constants ----------------
#define NB 16          // graphs (batch)
#define NUM_NODE 2048
#define NN 32768       // total nodes
#define EO 524288      // original edges
#define EPG 32768      // edges per graph (original)
#define ET 557056      // edges + self loops
#define ND 768         // node dim
#define ED 128         // edge dim / glob dim
#define EPSV 1e-5f

// ---------------- scratch (device globals; no allocation) ----------------
__device__ float  g_a192[192 * NN];   // K-major [192][NN]
__device__ float  g_a768[(size_t)NN * ND];
__device__ float  g_t[(size_t)NN * ND];
__device__ float  g_he[NN * ED];
__device__ float  g_z[NN * ED];
__device__ float  g_cmean[NB], g_cistd[NB];
__device__ double g_nsum[NB], g_nsq[NB];
__device__ float  g_nmean[NB], g_nistd[NB];
__device__ double g_esum[NB], g_esq[NB];
__device__ float  g_se[NB * ED], g_oe[NB * ED], g_bgp[NB * ED];
__device__ float  g_gsum[NB * ED];

// ---------------- helpers ----------------
__device__ __forceinline__ float block_reduce(float v, float* sm) {
#pragma unroll
    for (int o = 16; o; o >>= 1) v += __shfl_xor_sync(0xffffffffu, v, o);
    int lane = threadIdx.x & 31, w = threadIdx.x >> 5;
    if (lane == 0) sm[w] = v;
    __syncthreads();
    int nw = (blockDim.x + 31) >> 5;
    if (w == 0) {
        v = (lane < nw) ? sm[lane] : 0.f;
#pragma unroll
        for (int o = 16; o; o >>= 1) v += __shfl_xor_sync(0xffffffffu, v, o);
        if (lane == 0) sm[0] = v;
    }
    __syncthreads();
    v = sm[0];
    __syncthreads();
    return v;
}

// ---------------- kernels ----------------
__global__ void zero_stats_kernel() {
    int t = blockIdx.x * blockDim.x + threadIdx.x;
    if (t < NB) { g_nsum[t] = 0.0; g_nsq[t] = 0.0; g_esum[t] = 0.0; g_esq[t] = 0.0; }
    if (t < NB * ED) g_gsum[t] = 0.f;
}

// per-graph scalar mean/istd over x (2048*3 values)
__global__ void coord_stats_kernel(const float* __restrict__ x) {
    __shared__ float sm[32];
    int g = blockIdx.x;
    const float* xg = x + (size_t)g * NUM_NODE * 3;
    float s = 0.f, ss = 0.f;
    for (int i = threadIdx.x; i < NUM_NODE * 3; i += blockDim.x) {
        float v = xg[i]; s += v; ss += v * v;
    }
    s  = block_reduce(s, sm);
    ss = block_reduce(ss, sm);
    if (threadIdx.x == 0) {
        float mean = s / (float)(NUM_NODE * 3);
        float var  = ss / (float)(NUM_NODE * 3) - mean * mean;
        g_cmean[g] = mean;
        g_cistd[g] = rsqrtf(var + EPSV);
    }
}

// coord LN + MLP 3->12->48->192, output K-major a192[j][node]
__global__ __launch_bounds__(256) void node_mlp_kernel(
    const float* __restrict__ x,
    const float* __restrict__ W1, const float* __restrict__ b1,
    const float* __restrict__ W2, const float* __restrict__ b2,
    const float* __restrict__ W3, const float* __restrict__ b3,
    const float* __restrict__ wlc, const float* __restrict__ blc) {
    __shared__ float W1s[36], b1s[12], W2s[576], b2s[48], W3s[9216], b3s[192], wlcs[3], blcs[3];
    int tid = threadIdx.x;
    for (int i = tid; i < 36;   i += 256) W1s[i] = W1[i];
    for (int i = tid; i < 12;   i += 256) b1s[i] = b1[i];
    for (int i = tid; i < 576;  i += 256) W2s[i] = W2[i];
    for (int i = tid; i < 48;   i += 256) b2s[i] = b2[i];
    for (int i = tid; i < 9216; i += 256) W3s[i] = W3[i];
    for (int i = tid; i < 192;  i += 256) b3s[i] = b3[i];
    if (tid < 3) { wlcs[tid] = wlc[tid]; blcs[tid] = blc[tid]; }
    __syncthreads();

    int node = blockIdx.x * 256 + tid;
    int g = node >> 11;
    float mean = g_cmean[g], istd = g_cistd[g];
    float h0[3];
#pragma unroll
    for (int c = 0; c < 3; c++)
        h0[c] = (x[node * 3 + c] - mean) * istd * wlcs[c] + blcs[c];

    float v12[12];
#pragma unroll
    for (int j = 0; j < 12; j++) {
        float a = b1s[j];
#pragma unroll
        for (int c = 0; c < 3; c++) a += h0[c] * W1s[c * 12 + j];
        v12[j] = fmaxf(a, 0.f);
    }
    float v48[48];
#pragma unroll
    for (int j = 0; j < 48; j++) {
        float a = b2s[j];
#pragma unroll
        for (int k = 0; k < 12; k++) a += v12[k] * W2s[k * 48 + j];
        v48[j] = fmaxf(a, 0.f);
    }
    for (int j = 0; j < 192; j++) {
        float a = b3s[j];
#pragma unroll
        for (int k = 0; k < 48; k++) a += v48[k] * W3s[k * 192 + j];
        g_a192[(size_t)j * NN + node] = fmaxf(a, 0.f);   // coalesced across tid
    }
}

// GEMM A: a768 = relu(a192 @ W_pre4 + b). A is K-major [192][NN].
__global__ __launch_bounds__(256) void gemm_pre4_kernel(
    const float* __restrict__ W, const float* __restrict__ bias) {
    const int M = NN, K = 192, NF = ND;
    __shared__ float As[8][128];
    __shared__ float Bs[8][128];
    int tid = threadIdx.x;
    int bm = blockIdx.x * 128, bn = blockIdx.y * 128;
    int ty = tid >> 4, tx = tid & 15;
    float acc[8][8] = {};
    int lk = tid >> 5, lm = (tid & 31) << 2;

    for (int k0 = 0; k0 < K; k0 += 8) {
        float4 av = *(const float4*)(g_a192 + (size_t)(k0 + lk) * M + bm + lm);
        float4 bv = *(const float4*)(W + (size_t)(k0 + lk) * NF + bn + lm);
        __syncthreads();
        *(float4*)&As[lk][lm] = av;
        *(float4*)&Bs[lk][lm] = bv;
        __syncthreads();
#pragma unroll
        for (int kk = 0; kk < 8; kk++) {
            float a[8], b[8];
            *(float4*)&a[0] = *(float4*)&As[kk][ty * 8];
            *(float4*)&a[4] = *(float4*)&As[kk][ty * 8 + 4];
            *(float4*)&b[0] = *(float4*)&Bs[kk][tx * 8];
            *(float4*)&b[4] = *(float4*)&Bs[kk][tx * 8 + 4];
#pragma unroll
            for (int i = 0; i < 8; i++)
#pragma unroll
                for (int j = 0; j < 8; j++) acc[i][j] += a[i] * b[j];
        }
    }
#pragma unroll
    for (int i = 0; i < 8; i++) {
        int row = bm + ty * 8 + i;
#pragma unroll
        for (int j = 0; j < 8; j++) {
            int col = bn + tx * 8 + j;
            g_a768[(size_t)row * NF + col] = fmaxf(acc[i][j] + bias[col], 0.f);
        }
    }
}

// GEMM B: t = relu(a768 @ W_dense + b) + atom_emb + aa_emb; fused per-graph sum/sumsq
__global__ __launch_bounds__(256) void gemm_dense_kernel(
    const float* __restrict__ W, const float* __restrict__ bias,
    const int* __restrict__ atom_ids, const int* __restrict__ aa_ids,
    const float* __restrict__ atom_emb, const float* __restrict__ aa_emb) {
    const int K = ND, NF = ND;
    __shared__ float As[8][128];
    __shared__ float Bs[8][128];
    __shared__ float sm[32];
    int tid = threadIdx.x;
    int bm = blockIdx.x * 128, bn = blockIdx.y * 128;
    int ty = tid >> 4, tx = tid & 15;
    float acc[8][8] = {};
    int lar = tid >> 1, lac = (tid & 1) << 2;
    int lbk = tid >> 5, lbn = (tid & 31) << 2;

    for (int k0 = 0; k0 < K; k0 += 8) {
        float4 av = *(const float4*)(g_a768 + (size_t)(bm + lar) * K + k0 + lac);
        float4 bv = *(const float4*)(W + (size_t)(k0 + lbk) * NF + bn + lbn);
        __syncthreads();
        As[lac + 0][lar] = av.x; As[lac + 1][lar] = av.y;
        As[lac + 2][lar] = av.z; As[lac + 3][lar] = av.w;
        *(float4*)&Bs[lbk][lbn] = bv;
        __syncthreads();
#pragma unroll
        for (int kk = 0; kk < 8; kk++) {
            float a[8], b[8];
            *(float4*)&a[0] = *(float4*)&As[kk][ty * 8];
            *(float4*)&a[4] = *(float4*)&As[kk][ty * 8 + 4];
            *(float4*)&b[0] = *(float4*)&Bs[kk][tx * 8];
            *(float4*)&b[4] = *(float4*)&Bs[kk][tx * 8 + 4];
#pragma unroll
            for (int i = 0; i < 8; i++)
#pragma unroll
                for (int j = 0; j < 8; j++) acc[i][j] += a[i] * b[j];
        }
    }
    float ls = 0.f, lss = 0.f;
    int g = bm >> 11;  // 128-row tile never straddles a graph (2048 % 128 == 0)
#pragma unroll
    for (int i = 0; i < 8; i++) {
        int row = bm + ty * 8 + i;
        int at = atom_ids[row], aa = aa_ids[row];
#pragma unroll
        for (int j = 0; j < 8; j++) {
            int col = bn + tx * 8 + j;
            float v = fmaxf(acc[i][j] + bias[col], 0.f)
                    + atom_emb[(size_t)at * ND + col] + aa_emb[(size_t)aa * ND + col];
            g_t[(size_t)row * NF + col] = v;
            ls += v; lss += v * v;
        }
    }
    ls  = block_reduce(ls, sm);
    lss = block_reduce(lss, sm);
    if (tid == 0) {
        atomicAdd(&g_nsum[g], (double)ls);
        atomicAdd(&g_nsq[g], (double)lss);
    }
}

__global__ void finalize_node_kernel() {
    int g = threadIdx.x;
    if (g >= NB) return;
    double denom = (double)NUM_NODE * (double)ND;
    float mean = (float)(g_nsum[g] / denom);
    float var  = (float)(g_nsq[g] / denom) - mean * mean;
    g_nmean[g] = mean;
    g_nistd[g] = rsqrtf(var + EPSV);
}

// GEMM C: h = LN(t) (written to output), he = relu(h @ W_edge + b_edge). NF=128, single col block.
__global__ __launch_bounds__(256) void gemm_edge_kernel(
    const float* __restrict__ W, const float* __restrict__ bias,
    const float* __restrict__ wln, const float* __restrict__ bln,
    float* __restrict__ h_out) {
    const int K = ND, NF = ED;
    __shared__ float As[8][128];
    __shared__ float Bs[8][128];
    int tid = threadIdx.x;
    int bm = blockIdx.x * 128;
    int ty = tid >> 4, tx = tid & 15;
    float acc[8][8] = {};
    int lar = tid >> 1, lac = (tid & 1) << 2;
    int lbk = tid >> 5, lbn = (tid & 31) << 2;
    int g = bm >> 11;
    float mean = g_nmean[g], istd = g_nistd[g];

    for (int k0 = 0; k0 < K; k0 += 8) {
        float4 av = *(const float4*)(g_t + (size_t)(bm + lar) * K + k0 + lac);
        float4 wv = *(const float4*)(wln + k0 + lac);
        float4 bv2 = *(const float4*)(bln + k0 + lac);
        float4 hv;
        hv.x = (av.x - mean) * istd * wv.x + bv2.x;
        hv.y = (av.y - mean) * istd * wv.y + bv2.y;
        hv.z = (av.z - mean) * istd * wv.z + bv2.z;
        hv.w = (av.w - mean) * istd * wv.w + bv2.w;
        *(float4*)(h_out + (size_t)(bm + lar) * ND + k0 + lac) = hv;  // each element written once
        float4 bvw = *(const float4*)(W + (size_t)(k0 + lbk) * NF + lbn);
        __syncthreads();
        As[lac + 0][lar] = hv.x; As[lac + 1][lar] = hv.y;
        As[lac + 2][lar] = hv.z; As[lac + 3][lar] = hv.w;
        *(float4*)&Bs[lbk][lbn] = bvw;
        __syncthreads();
#pragma unroll
        for (int kk = 0; kk < 8; kk++) {
            float a[8], b[8];
            *(float4*)&a[0] = *(float4*)&As[kk][ty * 8];
            *(float4*)&a[4] = *(float4*)&As[kk][ty * 8 + 4];
            *(float4*)&b[0] = *(float4*)&Bs[kk][tx * 8];
            *(float4*)&b[4] = *(float4*)&Bs[kk][tx * 8 + 4];
#pragma unroll
            for (int i = 0; i < 8; i++)
#pragma unroll
                for (int j = 0; j < 8; j++) acc[i][j] += a[i] * b[j];
        }
    }
#pragma unroll
    for (int i = 0; i < 8; i++) {
        int row = bm + ty * 8 + i;
#pragma unroll
        for (int j = 0; j < 8; j++) {
            int col = tx * 8 + j;
            g_he[(size_t)row * NF + col] = fmaxf(acc[i][j] + bias[col], 0.f);
        }
    }
}

// per-graph edge sum/sumsq over e = 0.5*(he[row]+he[col]); 256-edge block never straddles graphs
__global__ void edge_stats_kernel(const int* __restrict__ rowi, const int* __restrict__ coli) {
    __shared__ float sm[32];
    int e = blockIdx.x * 256 + threadIdx.x;
    int r, c, g;
    if (e < EO) { r = rowi[e]; c = coli[e]; g = e >> 15; }
    else        { int i = e - EO; r = i; c = i; g = i >> 11; }
    const float4* hr = (const float4*)(g_he + (size_t)r * ED);
    const float4* hc = (const float4*)(g_he + (size_t)c * ED);
    float s = 0.f, ss = 0.f;
#pragma unroll 8
    for (int q = 0; q < 32; q++) {
        float4 a = hr[q], b = hc[q];
        float v;
        v = 0.5f * (a.x + b.x); s += v; ss += v * v;
        v = 0.5f * (a.y + b.y); s += v; ss += v * v;
        v = 0.5f * (a.z + b.z); s += v; ss += v * v;
        v = 0.5f * (a.w + b.w); s += v; ss += v * v;
    }
    s  = block_reduce(s, sm);
    ss = block_reduce(ss, sm);
    if (threadIdx.x == 0) {
        atomicAdd(&g_esum[g], (double)s);
        atomicAdd(&g_esq[g], (double)ss);
    }
}

// per-graph edge-LN affine params + folded global bias bg' = o_e @ W_glob + b_glob
__global__ void edge_params_kernel(
    const float* __restrict__ wle, const float* __restrict__ ble,
    const float* __restrict__ Wg, const float* __restrict__ bg) {
    __shared__ float oesh[ED];
    int g = blockIdx.x, f = threadIdx.x;
    double denom = (double)(EPG + NUM_NODE) * (double)ED;  // 34816*128
    float mean = (float)(g_esum[g] / denom);
    float var  = (float)(g_esq[g] / denom) - mean * mean;
    float istd = rsqrtf(var + EPSV);
    float s = istd * wle[f];
    float o = ble[f] - mean * s;
    g_se[g * ED + f] = s;
    g_oe[g * ED + f] = o;
    oesh[f] = o;
    __syncthreads();
    float acc = bg[f];
#pragma unroll 8
    for (int k = 0; k < ED; k++) acc += oesh[k] * Wg[k * ED + f];
    g_bgp[g * ED + f] = acc;
}

// GEMM D: z = (s_e ⊙ he) @ W_glob  (per-node; 17x cheaper than edge-level)
__global__ __launch_bounds__(256) void gemm_z_kernel(const float* __restrict__ Wg) {
    const int K = ED, NF = ED;
    __shared__ float As[8][128];
    __shared__ float Bs[8][128];
    int tid = threadIdx.x;
    int bm = blockIdx.x * 128;
    int ty = tid >> 4, tx = tid & 15;
    float acc[8][8] = {};
    int lar = tid >> 1, lac = (tid & 1) << 2;
    int lbk = tid >> 5, lbn = (tid & 31) << 2;
    int g = bm >> 11;

    for (int k0 = 0; k0 < K; k0 += 8) {
        float4 av = *(const float4*)(g_he + (size_t)(bm + lar) * K + k0 + lac);
        float4 sv = *(const float4*)(g_se + g * ED + k0 + lac);
        float4 bvw = *(const float4*)(Wg + (size_t)(k0 + lbk) * NF + lbn);
        __syncthreads();
        As[lac + 0][lar] = av.x * sv.x; As[lac + 1][lar] = av.y * sv.y;
        As[lac + 2][lar] = av.z * sv.z; As[lac + 3][lar] = av.w * sv.w;
        *(float4*)&Bs[lbk][lbn] = bvw;
        __syncthreads();
#pragma unroll
        for (int kk = 0; kk < 8; kk++) {
            float a[8], b[8];
            *(float4*)&a[0] = *(float4*)&As[kk][ty * 8];
            *(float4*)&a[4] = *(float4*)&As[kk][ty * 8 + 4];
            *(float4*)&b[0] = *(float4*)&Bs[kk][tx * 8];
            *(float4*)&b[4] = *(float4*)&Bs[kk][tx * 8 + 4];
#pragma unroll
            for (int i = 0; i < 8; i++)
#pragma unroll
                for (int j = 0; j < 8; j++) acc[i][j] += a[i] * b[j];
        }
    }
#pragma unroll
    for (int i = 0; i < 8; i++) {
        int row = bm + ty * 8 + i;
#pragma unroll
        for (int j = 0; j < 8; j++)
            g_z[(size_t)row * NF + tx * 8 + j] = acc[i][j];
    }
}

// per edge: write edge_attr, accumulate per-graph sum of g = relu((z_r+z_c)/2 + bg')
__global__ void edge_write_kernel(const int* __restrict__ rowi, const int* __restrict__ coli,
                                  float* __restrict__ edge_out) {
    __shared__ int sr[64], sc[64];
    int e0 = blockIdx.x * 64;
    int f = threadIdx.x;
    int g = (e0 < EO) ? (e0 >> 15) : ((e0 - EO) >> 11);
    if (f < 64) {
        int e = e0 + f;
        if (e < EO) { sr[f] = rowi[e]; sc[f] = coli[e]; }
        else        { sr[f] = e - EO; sc[f] = e - EO; }
    }
    __syncthreads();
    float s = g_se[g * ED + f], o = g_oe[g * ED + f], bgp = g_bgp[g * ED + f];
    float acc = 0.f;
#pragma unroll 4
    for (int q = 0; q < 64; q++) {
        int r = sr[q], c = sc[q];
        float hv = 0.5f * (g_he[(size_t)r * ED + f] + g_he[(size_t)c * ED + f]);
        edge_out[(size_t)(e0 + q) * ED + f] = s * hv + o;
        float zv = 0.5f * (g_z[(size_t)r * ED + f] + g_z[(size_t)c * ED + f]) + bgp;
        acc += fmaxf(zv, 0.f);
    }
    atomicAdd(&g_gsum[g * ED + f], acc);
}

// global pooling mean + LN over 128 features per graph
__global__ void global_kernel(const float* __restrict__ wlg, const float* __restrict__ blg,
                              float* __restrict__ u_out) {
    __shared__ float sm[32];
    int g = blockIdx.x, f = threadIdx.x;
    float p = g_gsum[g * ED + f] / (float)(EPG + NUM_NODE);
    float s1 = block_reduce(p, sm);
    float s2 = block_reduce(p * p, sm);
    float mean = s1 / (float)ED;
    float var  = s2 / (float)ED - mean * mean;
    u_out[g * ED + f] = (p - mean) * rsqrtf(var + EPSV) * wlg[f] + blg[f];
}

// ---------------- launch ----------------
extern "C" void kernel_launch(void* const* d_in, const int* in_sizes, int n_in,
                              void* d_out, int out_size) {
    (void)in_sizes; (void)n_in; (void)out_size;
    const float* x        = (const float*)d_in[0];
    const int*   atom_ids = (const int*)  d_in[1];
    const int*   aa_ids   = (const int*)  d_in[2];
    const int*   ei       = (const int*)  d_in[3];
    const float* W1 = (const float*)d_in[4];  const float* b1 = (const float*)d_in[5];
    const float* W2 = (const float*)d_in[6];  const float* b2 = (const float*)d_in[7];
    const float* W3 = (const float*)d_in[8];  const float* b3 = (const float*)d_in[9];
    const float* W4 = (const float*)d_in[10]; const float* b4 = (const float*)d_in[11];
    const float* Wd = (const float*)d_in[12]; const float* bd = (const float*)d_in[13];
    const float* atom_emb = (const float*)d_in[14];
    const float* aa_emb   = (const float*)d_in[15];
    const float* wlc = (const float*)d_in[16]; const float* blc = (const float*)d_in[17];
    const float* wln = (const float*)d_in[18]; const float* bln = (const float*)d_in[19];
    const float* We  = (const float*)d_in[20]; const float* be  = (const float*)d_in[21];
    const float* wle = (const float*)d_in[22]; const float* ble = (const float*)d_in[23];
    const float* Wg  = (const float*)d_in[24]; const float* bg  = (const float*)d_in[25];
    const float* wlg = (const float*)d_in[26]; const float* blg = (const float*)d_in[27];

    float* out      = (float*)d_out;
    float* h_out    = out;
    float* edge_out = out + (size_t)NN * ND;
    float* u_out    = edge_out + (size_t)ET * ED;

    const int* ei_row = ei;
    const int* ei_col = ei + EO;

    zero_stats_kernel<<<8, 256>>>();
    coord_stats_kernel<<<NB, 256>>>(x);
    node_mlp_kernel<<<NN / 256, 256>>>(x, W1, b1, W2, b2, W3, b3, wlc, blc);
    gemm_pre4_kernel<<<dim3(NN / 128, ND / 128), 256>>>(W4, b4);
    gemm_dense_kernel<<<dim3(NN / 128, ND / 128), 256>>>(Wd, bd, atom_ids, aa_ids, atom_emb, aa_emb);
    finalize_node_kernel<<<1, NB>>>();
    gemm_edge_kernel<<<NN / 128, 256>>>(We, be, wln, bln, h_out);
    edge_stats_kernel<<<ET / 256, 256>>>(ei_row, ei_col);
    edge_params_kernel<<<NB, ED>>>(wle, ble, Wg, bg);
    gemm_z_kernel<<<NN / 128, 256>>>(Wg);
    edge_write_kernel<<<ET / 64, ED>>>(ei_row, ei_col, edge_out);
    global_kernel<<<NB, ED>>>(wlg, blg, u_out);
}

// round 2
// speedup vs baseline: 1.1284x; 1.1284x over previous
#include <cuda_runtime.h>

// ---------------- problem constants ----------------
#define NB 16          // graphs (batch)
#define NUM_NODE 2048
#define NN 32768       // total nodes
#define EO 524288      // original edges
#define EPG 32768      // edges per graph (original)
#define ET 557056      // edges + self loops
#define ND 768         // node dim
#define ED 128         // edge dim / glob dim
#define EPSV 1e-5f
#define SMP 132        // padded smem row stride (floats)

// ---------------- scratch (device globals; no allocation) ----------------
__device__ float  g_a192[192 * NN];   // K-major [192][NN]
__device__ float  g_a768[(size_t)NN * ND];
__device__ float  g_t[(size_t)NN * ND];
__device__ float  g_he[NN * ED];
__device__ float  g_z[NN * ED];
__device__ float  g_cmean[NB], g_cistd[NB];
__device__ double g_nsum[NB], g_nsq[NB];
__device__ float  g_nmean[NB], g_nistd[NB];
__device__ double g_esum[NB], g_esq[NB];
__device__ float  g_se[NB * ED], g_oe[NB * ED], g_bgp[NB * ED];
__device__ float  g_gsum[NB * ED];

// ---------------- helpers ----------------
__device__ __forceinline__ float block_reduce(float v, float* sm) {
#pragma unroll
    for (int o = 16; o; o >>= 1) v += __shfl_xor_sync(0xffffffffu, v, o);
    int lane = threadIdx.x & 31, w = threadIdx.x >> 5;
    if (lane == 0) sm[w] = v;
    __syncthreads();
    int nw = (blockDim.x + 31) >> 5;
    if (w == 0) {
        v = (lane < nw) ? sm[lane] : 0.f;
#pragma unroll
        for (int o = 16; o; o >>= 1) v += __shfl_xor_sync(0xffffffffu, v, o);
        if (lane == 0) sm[0] = v;
    }
    __syncthreads();
    v = sm[0];
    __syncthreads();
    return v;
}

#define FRAG_LOAD(As, Bs, cur, kk, a, b)                                  \
    *(float4*)&a[0] = *(float4*)&As[cur][kk][ty * 4];                     \
    *(float4*)&a[4] = *(float4*)&As[cur][kk][64 + ty * 4];                \
    *(float4*)&b[0] = *(float4*)&Bs[cur][kk][tx * 4];                     \
    *(float4*)&b[4] = *(float4*)&Bs[cur][kk][64 + tx * 4];

#define FMA_8x8(acc, a, b)                                                \
    _Pragma("unroll")                                                     \
    for (int i = 0; i < 8; i++)                                           \
        _Pragma("unroll")                                                 \
        for (int j = 0; j < 8; j++) acc[i][j] += a[i] * b[j];

// ---------------- kernels ----------------
__global__ void zero_stats_kernel() {
    int t = blockIdx.x * blockDim.x + threadIdx.x;
    if (t < NB) { g_nsum[t] = 0.0; g_nsq[t] = 0.0; g_esum[t] = 0.0; g_esq[t] = 0.0; }
    if (t < NB * ED) g_gsum[t] = 0.f;
}

// per-graph scalar mean/istd over x (2048*3 values)
__global__ void coord_stats_kernel(const float* __restrict__ x) {
    __shared__ float sm[32];
    int g = blockIdx.x;
    const float* xg = x + (size_t)g * NUM_NODE * 3;
    float s = 0.f, ss = 0.f;
    for (int i = threadIdx.x; i < NUM_NODE * 3; i += blockDim.x) {
        float v = xg[i]; s += v; ss += v * v;
    }
    s  = block_reduce(s, sm);
    ss = block_reduce(ss, sm);
    if (threadIdx.x == 0) {
        float mean = s / (float)(NUM_NODE * 3);
        float var  = ss / (float)(NUM_NODE * 3) - mean * mean;
        g_cmean[g] = mean;
        g_cistd[g] = rsqrtf(var + EPSV);
    }
}

// coord LN + MLP 3->12->48->192, output K-major a192[j][node]
__global__ __launch_bounds__(256) void node_mlp_kernel(
    const float* __restrict__ x,
    const float* __restrict__ W1, const float* __restrict__ b1,
    const float* __restrict__ W2, const float* __restrict__ b2,
    const float* __restrict__ W3, const float* __restrict__ b3,
    const float* __restrict__ wlc, const float* __restrict__ blc) {
    __shared__ float W1s[36], b1s[12], W2s[576], b2s[48], W3s[9216], b3s[192], wlcs[3], blcs[3];
    int tid = threadIdx.x;
    for (int i = tid; i < 36;   i += 256) W1s[i] = W1[i];
    for (int i = tid; i < 12;   i += 256) b1s[i] = b1[i];
    for (int i = tid; i < 576;  i += 256) W2s[i] = W2[i];
    for (int i = tid; i < 48;   i += 256) b2s[i] = b2[i];
    for (int i = tid; i < 9216; i += 256) W3s[i] = W3[i];
    for (int i = tid; i < 192;  i += 256) b3s[i] = b3[i];
    if (tid < 3) { wlcs[tid] = wlc[tid]; blcs[tid] = blc[tid]; }
    __syncthreads();

    int node = blockIdx.x * 256 + tid;
    int g = node >> 11;
    float mean = g_cmean[g], istd = g_cistd[g];
    float h0[3];
#pragma unroll
    for (int c = 0; c < 3; c++)
        h0[c] = (x[node * 3 + c] - mean) * istd * wlcs[c] + blcs[c];

    float v12[12];
#pragma unroll
    for (int j = 0; j < 12; j++) {
        float a = b1s[j];
#pragma unroll
        for (int c = 0; c < 3; c++) a += h0[c] * W1s[c * 12 + j];
        v12[j] = fmaxf(a, 0.f);
    }
    float v48[48];
#pragma unroll
    for (int j = 0; j < 48; j++) {
        float a = b2s[j];
#pragma unroll
        for (int k = 0; k < 12; k++) a += v12[k] * W2s[k * 48 + j];
        v48[j] = fmaxf(a, 0.f);
    }
    for (int j = 0; j < 192; j++) {
        float a = b3s[j];
#pragma unroll
        for (int k = 0; k < 48; k++) a += v48[k] * W3s[k * 192 + j];
        g_a192[(size_t)j * NN + node] = fmaxf(a, 0.f);   // coalesced across tid
    }
}

// GEMM A: a768 = relu(a192 @ W_pre4 + b). A is K-major [192][NN].
// 2-stage pipeline, padded smem, conflict-free frags.
__global__ __launch_bounds__(256) void gemm_pre4_kernel(
    const float* __restrict__ W, const float* __restrict__ bias) {
    const int M = NN, K = 192, NF = ND;
    __shared__ float As[2][8][SMP];
    __shared__ float Bs[2][8][SMP];
    int tid = threadIdx.x;
    int bm = blockIdx.x * 128, bn = blockIdx.y * 128;
    int ty = tid >> 4, tx = tid & 15;
    int lk = tid >> 5, lm = (tid & 31) << 2;
    float acc[8][8] = {};

    float4 av = *(const float4*)(g_a192 + (size_t)lk * M + bm + lm);
    float4 bv = *(const float4*)(W + (size_t)lk * NF + bn + lm);
    *(float4*)&As[0][lk][lm] = av;
    *(float4*)&Bs[0][lk][lm] = bv;

    const int T = K / 8;
    for (int it = 0; it < T; ++it) {
        if (it + 1 < T) {
            int k0 = (it + 1) * 8;
            av = *(const float4*)(g_a192 + (size_t)(k0 + lk) * M + bm + lm);
            bv = *(const float4*)(W + (size_t)(k0 + lk) * NF + bn + lm);
        }
        __syncthreads();
        int cur = it & 1;
#pragma unroll
        for (int kk = 0; kk < 8; kk++) {
            float a[8], b[8];
            FRAG_LOAD(As, Bs, cur, kk, a, b)
            FMA_8x8(acc, a, b)
        }
        if (it + 1 < T) {
            int nxt = cur ^ 1;
            *(float4*)&As[nxt][lk][lm] = av;
            *(float4*)&Bs[nxt][lk][lm] = bv;
        }
    }
#pragma unroll
    for (int i = 0; i < 8; i++) {
        int row = bm + ((i < 4) ? ty * 4 + i : 64 + ty * 4 + i - 4);
#pragma unroll
        for (int jh = 0; jh < 2; jh++) {
            int col = bn + jh * 64 + tx * 4;
            float4 o;
            o.x = fmaxf(acc[i][jh * 4 + 0] + bias[col + 0], 0.f);
            o.y = fmaxf(acc[i][jh * 4 + 1] + bias[col + 1], 0.f);
            o.z = fmaxf(acc[i][jh * 4 + 2] + bias[col + 2], 0.f);
            o.w = fmaxf(acc[i][jh * 4 + 3] + bias[col + 3], 0.f);
            *(float4*)(g_a768 + (size_t)row * NF + col) = o;
        }
    }
}

// GEMM B: t = relu(a768 @ W_dense + b) + atom_emb + aa_emb; fused per-graph sum/sumsq
__global__ __launch_bounds__(256) void gemm_dense_kernel(
    const float* __restrict__ W, const float* __restrict__ bias,
    const int* __restrict__ atom_ids, const int* __restrict__ aa_ids,
    const float* __restrict__ atom_emb, const float* __restrict__ aa_emb) {
    const int K = ND, NF = ND;
    __shared__ float As[2][8][SMP];
    __shared__ float Bs[2][8][SMP];
    __shared__ float sm[32];
    int tid = threadIdx.x;
    int bm = blockIdx.x * 128, bn = blockIdx.y * 128;
    int ty = tid >> 4, tx = tid & 15;
    int lar = tid >> 1, lac = (tid & 1) << 2;
    int lbk = tid >> 5, lbn = (tid & 31) << 2;
    float acc[8][8] = {};

    float4 av = *(const float4*)(g_a768 + (size_t)(bm + lar) * K + lac);
    float4 bv = *(const float4*)(W + (size_t)lbk * NF + bn + lbn);
    As[0][lac + 0][lar] = av.x; As[0][lac + 1][lar] = av.y;
    As[0][lac + 2][lar] = av.z; As[0][lac + 3][lar] = av.w;
    *(float4*)&Bs[0][lbk][lbn] = bv;

    const int T = K / 8;
    for (int it = 0; it < T; ++it) {
        if (it + 1 < T) {
            int k0 = (it + 1) * 8;
            av = *(const float4*)(g_a768 + (size_t)(bm + lar) * K + k0 + lac);
            bv = *(const float4*)(W + (size_t)(k0 + lbk) * NF + bn + lbn);
        }
        __syncthreads();
        int cur = it & 1;
#pragma unroll
        for (int kk = 0; kk < 8; kk++) {
            float a[8], b[8];
            FRAG_LOAD(As, Bs, cur, kk, a, b)
            FMA_8x8(acc, a, b)
        }
        if (it + 1 < T) {
            int nxt = cur ^ 1;
            As[nxt][lac + 0][lar] = av.x; As[nxt][lac + 1][lar] = av.y;
            As[nxt][lac + 2][lar] = av.z; As[nxt][lac + 3][lar] = av.w;
            *(float4*)&Bs[nxt][lbk][lbn] = bv;
        }
    }
    float ls = 0.f, lss = 0.f;
    int g = bm >> 11;  // 128-row tile never straddles a graph (2048 % 128 == 0)
#pragma unroll
    for (int i = 0; i < 8; i++) {
        int row = bm + ((i < 4) ? ty * 4 + i : 64 + ty * 4 + i - 4);
        int at = atom_ids[row], aa = aa_ids[row];
#pragma unroll
        for (int jh = 0; jh < 2; jh++) {
            int col = bn + jh * 64 + tx * 4;
            float4 o;
            float* op = &o.x;
#pragma unroll
            for (int q = 0; q < 4; q++) {
                float v = fmaxf(acc[i][jh * 4 + q] + bias[col + q], 0.f)
                        + atom_emb[(size_t)at * ND + col + q]
                        + aa_emb[(size_t)aa * ND + col + q];
                op[q] = v;
                ls += v; lss += v * v;
            }
            *(float4*)(g_t + (size_t)row * NF + col) = o;
        }
    }
    ls  = block_reduce(ls, sm);
    lss = block_reduce(lss, sm);
    if (tid == 0) {
        atomicAdd(&g_nsum[g], (double)ls);
        atomicAdd(&g_nsq[g], (double)lss);
    }
}

__global__ void finalize_node_kernel() {
    int g = threadIdx.x;
    if (g >= NB) return;
    double denom = (double)NUM_NODE * (double)ND;
    float mean = (float)(g_nsum[g] / denom);
    float var  = (float)(g_nsq[g] / denom) - mean * mean;
    g_nmean[g] = mean;
    g_nistd[g] = rsqrtf(var + EPSV);
}

// GEMM C: h = LN(t) (written to output), he = relu(h @ W_edge + b_edge). NF=128.
__global__ __launch_bounds__(256) void gemm_edge_kernel(
    const float* __restrict__ W, const float* __restrict__ bias,
    const float* __restrict__ wln, const float* __restrict__ bln,
    float* __restrict__ h_out) {
    const int K = ND, NF = ED;
    __shared__ float As[2][8][SMP];
    __shared__ float Bs[2][8][SMP];
    int tid = threadIdx.x;
    int bm = blockIdx.x * 128;
    int ty = tid >> 4, tx = tid & 15;
    int lar = tid >> 1, lac = (tid & 1) << 2;
    int lbk = tid >> 5, lbn = (tid & 31) << 2;
    float acc[8][8] = {};
    int g = bm >> 11;
    float mean = g_nmean[g], istd = g_nistd[g];

    // prologue: LN-transform + stash
    float4 av = *(const float4*)(g_t + (size_t)(bm + lar) * K + lac);
    float4 wv = *(const float4*)(wln + lac);
    float4 bv2 = *(const float4*)(bln + lac);
    float4 hv;
    hv.x = (av.x - mean) * istd * wv.x + bv2.x;
    hv.y = (av.y - mean) * istd * wv.y + bv2.y;
    hv.z = (av.z - mean) * istd * wv.z + bv2.z;
    hv.w = (av.w - mean) * istd * wv.w + bv2.w;
    *(float4*)(h_out + (size_t)(bm + lar) * ND + lac) = hv;
    float4 bvw = *(const float4*)(W + (size_t)lbk * NF + lbn);
    As[0][lac + 0][lar] = hv.x; As[0][lac + 1][lar] = hv.y;
    As[0][lac + 2][lar] = hv.z; As[0][lac + 3][lar] = hv.w;
    *(float4*)&Bs[0][lbk][lbn] = bvw;

    const int T = K / 8;
    for (int it = 0; it < T; ++it) {
        if (it + 1 < T) {
            int k0 = (it + 1) * 8;
            av = *(const float4*)(g_t + (size_t)(bm + lar) * K + k0 + lac);
            wv = *(const float4*)(wln + k0 + lac);
            bv2 = *(const float4*)(bln + k0 + lac);
            hv.x = (av.x - mean) * istd * wv.x + bv2.x;
            hv.y = (av.y - mean) * istd * wv.y + bv2.y;
            hv.z = (av.z - mean) * istd * wv.z + bv2.z;
            hv.w = (av.w - mean) * istd * wv.w + bv2.w;
            *(float4*)(h_out + (size_t)(bm + lar) * ND + k0 + lac) = hv;
            bvw = *(const float4*)(W + (size_t)(k0 + lbk) * NF + lbn);
        }
        __syncthreads();
        int cur = it & 1;
#pragma unroll
        for (int kk = 0; kk < 8; kk++) {
            float a[8], b[8];
            FRAG_LOAD(As, Bs, cur, kk, a, b)
            FMA_8x8(acc, a, b)
        }
        if (it + 1 < T) {
            int nxt = cur ^ 1;
            As[nxt][lac + 0][lar] = hv.x; As[nxt][lac + 1][lar] = hv.y;
            As[nxt][lac + 2][lar] = hv.z; As[nxt][lac + 3][lar] = hv.w;
            *(float4*)&Bs[nxt][lbk][lbn] = bvw;
        }
    }
#pragma unroll
    for (int i = 0; i < 8; i++) {
        int row = bm + ((i < 4) ? ty * 4 + i : 64 + ty * 4 + i - 4);
#pragma unroll
        for (int jh = 0; jh < 2; jh++) {
            int col = jh * 64 + tx * 4;
            float4 o;
            o.x = fmaxf(acc[i][jh * 4 + 0] + bias[col + 0], 0.f);
            o.y = fmaxf(acc[i][jh * 4 + 1] + bias[col + 1], 0.f);
            o.z = fmaxf(acc[i][jh * 4 + 2] + bias[col + 2], 0.f);
            o.w = fmaxf(acc[i][jh * 4 + 3] + bias[col + 3], 0.f);
            *(float4*)(g_he + (size_t)row * NF + col) = o;
        }
    }
}

// per-graph edge sum/sumsq over e = 0.5*(he[row]+he[col])
__global__ void edge_stats_kernel(const int* __restrict__ rowi, const int* __restrict__ coli) {
    __shared__ float sm[32];
    int e = blockIdx.x * 256 + threadIdx.x;
    int r, c, g;
    if (e < EO) { r = rowi[e]; c = coli[e]; g = e >> 15; }
    else        { int i = e - EO; r = i; c = i; g = i >> 11; }
    const float4* hr = (const float4*)(g_he + (size_t)r * ED);
    const float4* hc = (const float4*)(g_he + (size_t)c * ED);
    float s = 0.f, ss = 0.f;
#pragma unroll 8
    for (int q = 0; q < 32; q++) {
        float4 a = hr[q], b = hc[q];
        float v;
        v = 0.5f * (a.x + b.x); s += v; ss += v * v;
        v = 0.5f * (a.y + b.y); s += v; ss += v * v;
        v = 0.5f * (a.z + b.z); s += v; ss += v * v;
        v = 0.5f * (a.w + b.w); s += v; ss += v * v;
    }
    s  = block_reduce(s, sm);
    ss = block_reduce(ss, sm);
    if (threadIdx.x == 0) {
        atomicAdd(&g_esum[g], (double)s);
        atomicAdd(&g_esq[g], (double)ss);
    }
}

// per-graph edge-LN affine params + folded global bias bg' = o_e @ W_glob + b_glob
__global__ void edge_params_kernel(
    const float* __restrict__ wle, const float* __restrict__ ble,
    const float* __restrict__ Wg, const float* __restrict__ bg) {
    __shared__ float oesh[ED];
    int g = blockIdx.x, f = threadIdx.x;
    double denom = (double)(EPG + NUM_NODE) * (double)ED;  // 34816*128
    float mean = (float)(g_esum[g] / denom);
    float var  = (float)(g_esq[g] / denom) - mean * mean;
    float istd = rsqrtf(var + EPSV);
    float s = istd * wle[f];
    float o = ble[f] - mean * s;
    g_se[g * ED + f] = s;
    g_oe[g * ED + f] = o;
    oesh[f] = o;
    __syncthreads();
    float acc = bg[f];
#pragma unroll 8
    for (int k = 0; k < ED; k++) acc += oesh[k] * Wg[k * ED + f];
    g_bgp[g * ED + f] = acc;
}

// GEMM D: z = (s_e ⊙ he) @ W_glob  (per-node; 17x cheaper than edge-level)
__global__ __launch_bounds__(256) void gemm_z_kernel(const float* __restrict__ Wg) {
    const int K = ED, NF = ED;
    __shared__ float As[2][8][SMP];
    __shared__ float Bs[2][8][SMP];
    int tid = threadIdx.x;
    int bm = blockIdx.x * 128;
    int ty = tid >> 4, tx = tid & 15;
    int lar = tid >> 1, lac = (tid & 1) << 2;
    int lbk = tid >> 5, lbn = (tid & 31) << 2;
    float acc[8][8] = {};
    int g = bm >> 11;

    float4 av = *(const float4*)(g_he + (size_t)(bm + lar) * K + lac);
    float4 sv = *(const float4*)(g_se + g * ED + lac);
    av.x *= sv.x; av.y *= sv.y; av.z *= sv.z; av.w *= sv.w;
    float4 bvw = *(const float4*)(Wg + (size_t)lbk * NF + lbn);
    As[0][lac + 0][lar] = av.x; As[0][lac + 1][lar] = av.y;
    As[0][lac + 2][lar] = av.z; As[0][lac + 3][lar] = av.w;
    *(float4*)&Bs[0][lbk][lbn] = bvw;

    const int T = K / 8;
    for (int it = 0; it < T; ++it) {
        if (it + 1 < T) {
            int k0 = (it + 1) * 8;
            av = *(const float4*)(g_he + (size_t)(bm + lar) * K + k0 + lac);
            sv = *(const float4*)(g_se + g * ED + k0 + lac);
            av.x *= sv.x; av.y *= sv.y; av.z *= sv.z; av.w *= sv.w;
            bvw = *(const float4*)(Wg + (size_t)(k0 + lbk) * NF + lbn);
        }
        __syncthreads();
        int cur = it & 1;
#pragma unroll
        for (int kk = 0; kk < 8; kk++) {
            float a[8], b[8];
            FRAG_LOAD(As, Bs, cur, kk, a, b)
            FMA_8x8(acc, a, b)
        }
        if (it + 1 < T) {
            int nxt = cur ^ 1;
            As[nxt][lac + 0][lar] = av.x; As[nxt][lac + 1][lar] = av.y;
            As[nxt][lac + 2][lar] = av.z; As[nxt][lac + 3][lar] = av.w;
            *(float4*)&Bs[nxt][lbk][lbn] = bvw;
        }
    }
#pragma unroll
    for (int i = 0; i < 8; i++) {
        int row = bm + ((i < 4) ? ty * 4 + i : 64 + ty * 4 + i - 4);
#pragma unroll
        for (int jh = 0; jh < 2; jh++) {
            int col = jh * 64 + tx * 4;
            float4 o;
            o.x = acc[i][jh * 4 + 0]; o.y = acc[i][jh * 4 + 1];
            o.z = acc[i][jh * 4 + 2]; o.w = acc[i][jh * 4 + 3];
            *(float4*)(g_z + (size_t)row * NF + col) = o;
        }
    }
}

// per edge: write edge_attr, accumulate per-graph sum of g = relu((z_r+z_c)/2 + bg')
__global__ void edge_write_kernel(const int* __restrict__ rowi, const int* __restrict__ coli,
                                  float* __restrict__ edge_out) {
    __shared__ int sr[64], sc[64];
    int e0 = blockIdx.x * 64;
    int f = threadIdx.x;
    int g = (e0 < EO) ? (e0 >> 15) : ((e0 - EO) >> 11);
    if (f < 64) {
        int e = e0 + f;
        if (e < EO) { sr[f] = rowi[e]; sc[f] = coli[e]; }
        else        { sr[f] = e - EO; sc[f] = e - EO; }
    }
    __syncthreads();
    float s = g_se[g * ED + f], o = g_oe[g * ED + f], bgp = g_bgp[g * ED + f];
    float acc = 0.f;
#pragma unroll 4
    for (int q = 0; q < 64; q++) {
        int r = sr[q], c = sc[q];
        float hv = 0.5f * (g_he[(size_t)r * ED + f] + g_he[(size_t)c * ED + f]);
        edge_out[(size_t)(e0 + q) * ED + f] = s * hv + o;
        float zv = 0.5f * (g_z[(size_t)r * ED + f] + g_z[(size_t)c * ED + f]) + bgp;
        acc += fmaxf(zv, 0.f);
    }
    atomicAdd(&g_gsum[g * ED + f], acc);
}

// global pooling mean + LN over 128 features per graph
__global__ void global_kernel(const float* __restrict__ wlg, const float* __restrict__ blg,
                              float* __restrict__ u_out) {
    __shared__ float sm[32];
    int g = blockIdx.x, f = threadIdx.x;
    float p = g_gsum[g * ED + f] / (float)(EPG + NUM_NODE);
    float s1 = block_reduce(p, sm);
    float s2 = block_reduce(p * p, sm);
    float mean = s1 / (float)ED;
    float var  = s2 / (float)ED - mean * mean;
    u_out[g * ED + f] = (p - mean) * rsqrtf(var + EPSV) * wlg[f] + blg[f];
}

// ---------------- launch ----------------
extern "C" void kernel_launch(void* const* d_in, const int* in_sizes, int n_in,
                              void* d_out, int out_size) {
    (void)in_sizes; (void)n_in; (void)out_size;
    const float* x        = (const float*)d_in[0];
    const int*   atom_ids = (const int*)  d_in[1];
    const int*   aa_ids   = (const int*)  d_in[2];
    const int*   ei       = (const int*)  d_in[3];
    const float* W1 = (const float*)d_in[4];  const float* b1 = (const float*)d_in[5];
    const float* W2 = (const float*)d_in[6];  const float* b2 = (const float*)d_in[7];
    const float* W3 = (const float*)d_in[8];  const float* b3 = (const float*)d_in[9];
    const float* W4 = (const float*)d_in[10]; const float* b4 = (const float*)d_in[11];
    const float* Wd = (const float*)d_in[12]; const float* bd = (const float*)d_in[13];
    const float* atom_emb = (const float*)d_in[14];
    const float* aa_emb   = (const float*)d_in[15];
    const float* wlc = (const float*)d_in[16]; const float* blc = (const float*)d_in[17];
    const float* wln = (const float*)d_in[18]; const float* bln = (const float*)d_in[19];
    const float* We  = (const float*)d_in[20]; const float* be  = (const float*)d_in[21];
    const float* wle = (const float*)d_in[22]; const float* ble = (const float*)d_in[23];
    const float* Wg  = (const float*)d_in[24]; const float* bg  = (const float*)d_in[25];
    const float* wlg = (const float*)d_in[26]; const float* blg = (const float*)d_in[27];

    float* out      = (float*)d_out;
    float* h_out    = out;
    float* edge_out = out + (size_t)NN * ND;
    float* u_out    = edge_out + (size_t)ET * ED;

    const int* ei_row = ei;
    const int* ei_col = ei + EO;

    zero_stats_kernel<<<8, 256>>>();
    coord_stats_kernel<<<NB, 256>>>(x);
    node_mlp_kernel<<<NN / 256, 256>>>(x, W1, b1, W2, b2, W3, b3, wlc, blc);
    gemm_pre4_kernel<<<dim3(NN / 128, ND / 128), 256>>>(W4, b4);
    gemm_dense_kernel<<<dim3(NN / 128, ND / 128), 256>>>(Wd, bd, atom_ids, aa_ids, atom_emb, aa_emb);
    finalize_node_kernel<<<1, NB>>>();
    gemm_edge_kernel<<<NN / 128, 256>>>(We, be, wln, bln, h_out);
    edge_stats_kernel<<<ET / 256, 256>>>(ei_row, ei_col);
    edge_params_kernel<<<NB, ED>>>(wle, ble, Wg, bg);
    gemm_z_kernel<<<NN / 128, 256>>>(Wg);
    edge_write_kernel<<<ET / 64, ED>>>(ei_row, ei_col, edge_out);
    global_kernel<<<NB, ED>>>(wlg, blg, u_out);
}

// round 13
// speedup vs baseline: 1.1589x; 1.0270x over previous
#include <cuda_runtime.h>
#include <cstdint>

// ---------------- problem constants ----------------
#define NB 16          // graphs (batch)
#define NUM_NODE 2048
#define NN 32768       // total nodes
#define EO 524288      // original edges
#define EPG 32768      // edges per graph (original)
#define ET 557056      // edges + self loops
#define ND 768         // node dim
#define ED 128         // edge dim / glob dim
#define EPSV 1e-5f
#define SMP 132        // padded smem row stride (floats); 132*4=528B = 16B-aligned rows

// ---------------- scratch (device globals; no allocation) ----------------
__device__ float  g_a192[192 * NN];   // K-major [192][NN]
__device__ float  g_a768[(size_t)NN * ND];
__device__ float  g_t[(size_t)NN * ND];
__device__ float  g_he[NN * ED];
__device__ float  g_z[NN * ED];
__device__ float  g_cmean[NB], g_cistd[NB];
__device__ double g_nsum[NB], g_nsq[NB];
__device__ float  g_nmean[NB], g_nistd[NB];
__device__ double g_esum[NB], g_esq[NB];
__device__ float  g_se[NB * ED], g_oe[NB * ED], g_bgp[NB * ED];
__device__ float  g_gsum[NB * ED];

// ---------------- helpers ----------------
__device__ __forceinline__ float block_reduce(float v, float* sm) {
#pragma unroll
    for (int o = 16; o; o >>= 1) v += __shfl_xor_sync(0xffffffffu, v, o);
    int lane = threadIdx.x & 31, w = threadIdx.x >> 5;
    if (lane == 0) sm[w] = v;
    __syncthreads();
    int nw = (blockDim.x + 31) >> 5;
    if (w == 0) {
        v = (lane < nw) ? sm[lane] : 0.f;
#pragma unroll
        for (int o = 16; o; o >>= 1) v += __shfl_xor_sync(0xffffffffu, v, o);
        if (lane == 0) sm[0] = v;
    }
    __syncthreads();
    v = sm[0];
    __syncthreads();
    return v;
}

// ---------------- packed f32x2 inner product (Blackwell FFMA2) ----------------
// b fragments as 64-bit lane pairs (consecutive floats), a broadcast per i.
#define FRAG_LOAD2(As, Bs, cur, kk, a, b2)                                \
    *(float4*)&a[0] = *(float4*)&As[cur][kk][ty * 4];                     \
    *(float4*)&a[4] = *(float4*)&As[cur][kk][64 + ty * 4];                \
    *(ulonglong2*)&b2[0] = *(const ulonglong2*)&Bs[cur][kk][tx * 4];      \
    *(ulonglong2*)&b2[2] = *(const ulonglong2*)&Bs[cur][kk][64 + tx * 4];

#define FMA2_8x8(acc2, a, b2)                                             \
    _Pragma("unroll")                                                     \
    for (int i = 0; i < 8; i++) {                                         \
        unsigned long long aa;                                            \
        asm("mov.b64 %0, {%1, %1};" : "=l"(aa) : "r"(__float_as_uint(a[i]))); \
        _Pragma("unroll")                                                 \
        for (int q = 0; q < 4; q++)                                       \
            asm("fma.rn.f32x2 %0, %1, %2, %0;"                            \
                : "+l"(acc2[i][q]) : "l"(aa), "l"(b2[q]));                \
    }

#define UNPK2(lo, hi, c) \
    asm("mov.b64 {%0, %1}, %2;" : "=r"(lo), "=r"(hi) : "l"(c));

// ---------------- kernels ----------------
__global__ void zero_stats_kernel() {
    int t = blockIdx.x * blockDim.x + threadIdx.x;
    if (t < NB) { g_nsum[t] = 0.0; g_nsq[t] = 0.0; g_esum[t] = 0.0; g_esq[t] = 0.0; }
    if (t < NB * ED) g_gsum[t] = 0.f;
}

__global__ void coord_stats_kernel(const float* __restrict__ x) {
    __shared__ float sm[32];
    int g = blockIdx.x;
    const float* xg = x + (size_t)g * NUM_NODE * 3;
    float s = 0.f, ss = 0.f;
    for (int i = threadIdx.x; i < NUM_NODE * 3; i += blockDim.x) {
        float v = xg[i]; s += v; ss += v * v;
    }
    s  = block_reduce(s, sm);
    ss = block_reduce(ss, sm);
    if (threadIdx.x == 0) {
        float mean = s / (float)(NUM_NODE * 3);
        float var  = ss / (float)(NUM_NODE * 3) - mean * mean;
        g_cmean[g] = mean;
        g_cistd[g] = rsqrtf(var + EPSV);
    }
}

// coord LN + MLP 3->12->48->192, output K-major a192[j][node]
__global__ __launch_bounds__(256) void node_mlp_kernel(
    const float* __restrict__ x,
    const float* __restrict__ W1, const float* __restrict__ b1,
    const float* __restrict__ W2, const float* __restrict__ b2,
    const float* __restrict__ W3, const float* __restrict__ b3,
    const float* __restrict__ wlc, const float* __restrict__ blc) {
    __shared__ float W1s[36], b1s[12], W2s[576], b2s[48], W3s[9216], b3s[192], wlcs[3], blcs[3];
    int tid = threadIdx.x;
    for (int i = tid; i < 36;   i += 256) W1s[i] = W1[i];
    for (int i = tid; i < 12;   i += 256) b1s[i] = b1[i];
    for (int i = tid; i < 576;  i += 256) W2s[i] = W2[i];
    for (int i = tid; i < 48;   i += 256) b2s[i] = b2[i];
    for (int i = tid; i < 9216; i += 256) W3s[i] = W3[i];
    for (int i = tid; i < 192;  i += 256) b3s[i] = b3[i];
    if (tid < 3) { wlcs[tid] = wlc[tid]; blcs[tid] = blc[tid]; }
    __syncthreads();

    int node = blockIdx.x * 256 + tid;
    int g = node >> 11;
    float mean = g_cmean[g], istd = g_cistd[g];
    float h0[3];
#pragma unroll
    for (int c = 0; c < 3; c++)
        h0[c] = (x[node * 3 + c] - mean) * istd * wlcs[c] + blcs[c];

    float v12[12];
#pragma unroll
    for (int j = 0; j < 12; j++) {
        float a = b1s[j];
#pragma unroll
        for (int c = 0; c < 3; c++) a += h0[c] * W1s[c * 12 + j];
        v12[j] = fmaxf(a, 0.f);
    }
    float v48[48];
#pragma unroll
    for (int j = 0; j < 48; j++) {
        float a = b2s[j];
#pragma unroll
        for (int k = 0; k < 12; k++) a += v12[k] * W2s[k * 48 + j];
        v48[j] = fmaxf(a, 0.f);
    }
    for (int j = 0; j < 192; j++) {
        float a = b3s[j];
#pragma unroll
        for (int k = 0; k < 48; k++) a += v48[k] * W3s[k * 192 + j];
        g_a192[(size_t)j * NN + node] = fmaxf(a, 0.f);   // coalesced across tid
    }
}

// GEMM A: a768 = relu(a192 @ W_pre4 + b). A is K-major [192][NN]. f32x2 inner product.
__global__ __launch_bounds__(256) void gemm_pre4_kernel(
    const float* __restrict__ W, const float* __restrict__ bias) {
    const int M = NN, K = 192, NF = ND;
    __shared__ float As[2][8][SMP];
    __shared__ float Bs[2][8][SMP];
    int tid = threadIdx.x;
    int bm = blockIdx.x * 128, bn = blockIdx.y * 128;
    int ty = tid >> 4, tx = tid & 15;
    int lk = tid >> 5, lm = (tid & 31) << 2;
    unsigned long long acc2[8][4] = {};

    float4 av = *(const float4*)(g_a192 + (size_t)lk * M + bm + lm);
    float4 bv = *(const float4*)(W + (size_t)lk * NF + bn + lm);
    *(float4*)&As[0][lk][lm] = av;
    *(float4*)&Bs[0][lk][lm] = bv;

    const int T = K / 8;
    for (int it = 0; it < T; ++it) {
        if (it + 1 < T) {
            int k0 = (it + 1) * 8;
            av = *(const float4*)(g_a192 + (size_t)(k0 + lk) * M + bm + lm);
            bv = *(const float4*)(W + (size_t)(k0 + lk) * NF + bn + lm);
        }
        __syncthreads();
        int cur = it & 1;
#pragma unroll
        for (int kk = 0; kk < 8; kk++) {
            float a[8];
            unsigned long long b2[4];
            FRAG_LOAD2(As, Bs, cur, kk, a, b2)
            FMA2_8x8(acc2, a, b2)
        }
        if (it + 1 < T) {
            int nxt = cur ^ 1;
            *(float4*)&As[nxt][lk][lm] = av;
            *(float4*)&Bs[nxt][lk][lm] = bv;
        }
    }
#pragma unroll
    for (int i = 0; i < 8; i++) {
        int row = bm + ((i < 4) ? ty * 4 + i : 64 + ty * 4 + i - 4);
#pragma unroll
        for (int jh = 0; jh < 2; jh++) {
            int col = bn + jh * 64 + tx * 4;
            uint32_t u0, u1, u2, u3;
            UNPK2(u0, u1, acc2[i][2 * jh + 0])
            UNPK2(u2, u3, acc2[i][2 * jh + 1])
            float4 o;
            o.x = fmaxf(__uint_as_float(u0) + bias[col + 0], 0.f);
            o.y = fmaxf(__uint_as_float(u1) + bias[col + 1], 0.f);
            o.z = fmaxf(__uint_as_float(u2) + bias[col + 2], 0.f);
            o.w = fmaxf(__uint_as_float(u3) + bias[col + 3], 0.f);
            *(float4*)(g_a768 + (size_t)row * NF + col) = o;
        }
    }
}

// GEMM B: t = relu(a768 @ W_dense + b) + atom_emb + aa_emb; fused per-graph sum/sumsq
__global__ __launch_bounds__(256) void gemm_dense_kernel(
    const float* __restrict__ W, const float* __restrict__ bias,
    const int* __restrict__ atom_ids, const int* __restrict__ aa_ids,
    const float* __restrict__ atom_emb, const float* __restrict__ aa_emb) {
    const int K = ND, NF = ND;
    __shared__ float As[2][8][SMP];
    __shared__ float Bs[2][8][SMP];
    __shared__ float sm[32];
    int tid = threadIdx.x;
    int bm = blockIdx.x * 128, bn = blockIdx.y * 128;
    int ty = tid >> 4, tx = tid & 15;
    int lar = tid >> 1, lac = (tid & 1) << 2;
    int lbk = tid >> 5, lbn = (tid & 31) << 2;
    unsigned long long acc2[8][4] = {};

    float4 av = *(const float4*)(g_a768 + (size_t)(bm + lar) * K + lac);
    float4 bv = *(const float4*)(W + (size_t)lbk * NF + bn + lbn);
    As[0][lac + 0][lar] = av.x; As[0][lac + 1][lar] = av.y;
    As[0][lac + 2][lar] = av.z; As[0][lac + 3][lar] = av.w;
    *(float4*)&Bs[0][lbk][lbn] = bv;

    const int T = K / 8;
    for (int it = 0; it < T; ++it) {
        if (it + 1 < T) {
            int k0 = (it + 1) * 8;
            av = *(const float4*)(g_a768 + (size_t)(bm + lar) * K + k0 + lac);
            bv = *(const float4*)(W + (size_t)(k0 + lbk) * NF + bn + lbn);
        }
        __syncthreads();
        int cur = it & 1;
#pragma unroll
        for (int kk = 0; kk < 8; kk++) {
            float a[8];
            unsigned long long b2[4];
            FRAG_LOAD2(As, Bs, cur, kk, a, b2)
            FMA2_8x8(acc2, a, b2)
        }
        if (it + 1 < T) {
            int nxt = cur ^ 1;
            As[nxt][lac + 0][lar] = av.x; As[nxt][lac + 1][lar] = av.y;
            As[nxt][lac + 2][lar] = av.z; As[nxt][lac + 3][lar] = av.w;
            *(float4*)&Bs[nxt][lbk][lbn] = bv;
        }
    }
    float ls = 0.f, lss = 0.f;
    int g = bm >> 11;  // 128-row tile never straddles a graph
#pragma unroll
    for (int i = 0; i < 8; i++) {
        int row = bm + ((i < 4) ? ty * 4 + i : 64 + ty * 4 + i - 4);
        int at = atom_ids[row], aa = aa_ids[row];
#pragma unroll
        for (int jh = 0; jh < 2; jh++) {
            int col = bn + jh * 64 + tx * 4;
            uint32_t u0, u1, u2, u3;
            UNPK2(u0, u1, acc2[i][2 * jh + 0])
            UNPK2(u2, u3, acc2[i][2 * jh + 1])
            float4 bb = *(const float4*)(bias + col);
            float4 ea = *(const float4*)(atom_emb + (size_t)at * ND + col);
            float4 eb = *(const float4*)(aa_emb + (size_t)aa * ND + col);
            float4 o;
            o.x = fmaxf(__uint_as_float(u0) + bb.x, 0.f) + ea.x + eb.x;
            o.y = fmaxf(__uint_as_float(u1) + bb.y, 0.f) + ea.y + eb.y;
            o.z = fmaxf(__uint_as_float(u2) + bb.z, 0.f) + ea.z + eb.z;
            o.w = fmaxf(__uint_as_float(u3) + bb.w, 0.f) + ea.w + eb.w;
            ls  += o.x + o.y + o.z + o.w;
            lss += o.x * o.x + o.y * o.y + o.z * o.z + o.w * o.w;
            *(float4*)(g_t + (size_t)row * NF + col) = o;
        }
    }
    ls  = block_reduce(ls, sm);
    lss = block_reduce(lss, sm);
    if (tid == 0) {
        atomicAdd(&g_nsum[g], (double)ls);
        atomicAdd(&g_nsq[g], (double)lss);
    }
}

__global__ void finalize_node_kernel() {
    int g = threadIdx.x;
    if (g >= NB) return;
    double denom = (double)NUM_NODE * (double)ND;
    float mean = (float)(g_nsum[g] / denom);
    float var  = (float)(g_nsq[g] / denom) - mean * mean;
    g_nmean[g] = mean;
    g_nistd[g] = rsqrtf(var + EPSV);
}

// GEMM C: h = LN(t) (written to output), he = relu(h @ W_edge + b_edge). NF=128.
__global__ __launch_bounds__(256) void gemm_edge_kernel(
    const float* __restrict__ W, const float* __restrict__ bias,
    const float* __restrict__ wln, const float* __restrict__ bln,
    float* __restrict__ h_out) {
    const int K = ND, NF = ED;
    __shared__ float As[2][8][SMP];
    __shared__ float Bs[2][8][SMP];
    int tid = threadIdx.x;
    int bm = blockIdx.x * 128;
    int ty = tid >> 4, tx = tid & 15;
    int lar = tid >> 1, lac = (tid & 1) << 2;
    int lbk = tid >> 5, lbn = (tid & 31) << 2;
    unsigned long long acc2[8][4] = {};
    int g = bm >> 11;
    float mean = g_nmean[g], istd = g_nistd[g];

    float4 av = *(const float4*)(g_t + (size_t)(bm + lar) * K + lac);
    float4 wv = *(const float4*)(wln + lac);
    float4 bv2 = *(const float4*)(bln + lac);
    float4 hv;
    hv.x = (av.x - mean) * istd * wv.x + bv2.x;
    hv.y = (av.y - mean) * istd * wv.y + bv2.y;
    hv.z = (av.z - mean) * istd * wv.z + bv2.z;
    hv.w = (av.w - mean) * istd * wv.w + bv2.w;
    *(float4*)(h_out + (size_t)(bm + lar) * ND + lac) = hv;
    float4 bvw = *(const float4*)(W + (size_t)lbk * NF + lbn);
    As[0][lac + 0][lar] = hv.x; As[0][lac + 1][lar] = hv.y;
    As[0][lac + 2][lar] = hv.z; As[0][lac + 3][lar] = hv.w;
    *(float4*)&Bs[0][lbk][lbn] = bvw;

    const int T = K / 8;
    for (int it = 0; it < T; ++it) {
        if (it + 1 < T) {
            int k0 = (it + 1) * 8;
            av = *(const float4*)(g_t + (size_t)(bm + lar) * K + k0 + lac);
            wv = *(const float4*)(wln + k0 + lac);
            bv2 = *(const float4*)(bln + k0 + lac);
            hv.x = (av.x - mean) * istd * wv.x + bv2.x;
            hv.y = (av.y - mean) * istd * wv.y + bv2.y;
            hv.z = (av.z - mean) * istd * wv.z + bv2.z;
            hv.w = (av.w - mean) * istd * wv.w + bv2.w;
            *(float4*)(h_out + (size_t)(bm + lar) * ND + k0 + lac) = hv;
            bvw = *(const float4*)(W + (size_t)(k0 + lbk) * NF + lbn);
        }
        __syncthreads();
        int cur = it & 1;
#pragma unroll
        for (int kk = 0; kk < 8; kk++) {
            float a[8];
            unsigned long long b2[4];
            FRAG_LOAD2(As, Bs, cur, kk, a, b2)
            FMA2_8x8(acc2, a, b2)
        }
        if (it + 1 < T) {
            int nxt = cur ^ 1;
            As[nxt][lac + 0][lar] = hv.x; As[nxt][lac + 1][lar] = hv.y;
            As[nxt][lac + 2][lar] = hv.z; As[nxt][lac + 3][lar] = hv.w;
            *(float4*)&Bs[nxt][lbk][lbn] = bvw;
        }
    }
#pragma unroll
    for (int i = 0; i < 8; i++) {
        int row = bm + ((i < 4) ? ty * 4 + i : 64 + ty * 4 + i - 4);
#pragma unroll
        for (int jh = 0; jh < 2; jh++) {
            int col = jh * 64 + tx * 4;
            uint32_t u0, u1, u2, u3;
            UNPK2(u0, u1, acc2[i][2 * jh + 0])
            UNPK2(u2, u3, acc2[i][2 * jh + 1])
            float4 o;
            o.x = fmaxf(__uint_as_float(u0) + bias[col + 0], 0.f);
            o.y = fmaxf(__uint_as_float(u1) + bias[col + 1], 0.f);
            o.z = fmaxf(__uint_as_float(u2) + bias[col + 2], 0.f);
            o.w = fmaxf(__uint_as_float(u3) + bias[col + 3], 0.f);
            *(float4*)(g_he + (size_t)row * NF + col) = o;
        }
    }
}

// per-graph edge sum/sumsq over e = 0.5*(he[row]+he[col])
__global__ void edge_stats_kernel(const int* __restrict__ rowi, const int* __restrict__ coli) {
    __shared__ float sm[32];
    int e = blockIdx.x * 256 + threadIdx.x;
    int r, c, g;
    if (e < EO) { r = rowi[e]; c = coli[e]; g = e >> 15; }
    else        { int i = e - EO; r = i; c = i; g = i >> 11; }
    const float4* hr = (const float4*)(g_he + (size_t)r * ED);
    const float4* hc = (const float4*)(g_he + (size_t)c * ED);
    float s = 0.f, ss = 0.f;
#pragma unroll 8
    for (int q = 0; q < 32; q++) {
        float4 a = hr[q], b = hc[q];
        float v;
        v = 0.5f * (a.x + b.x); s += v; ss += v * v;
        v = 0.5f * (a.y + b.y); s += v; ss += v * v;
        v = 0.5f * (a.z + b.z); s += v; ss += v * v;
        v = 0.5f * (a.w + b.w); s += v; ss += v * v;
    }
    s  = block_reduce(s, sm);
    ss = block_reduce(ss, sm);
    if (threadIdx.x == 0) {
        atomicAdd(&g_esum[g], (double)s);
        atomicAdd(&g_esq[g], (double)ss);
    }
}

// per-graph edge-LN affine params + folded global bias bg' = o_e @ W_glob + b_glob
__global__ void edge_params_kernel(
    const float* __restrict__ wle, const float* __restrict__ ble,
    const float* __restrict__ Wg, const float* __restrict__ bg) {
    __shared__ float oesh[ED];
    int g = blockIdx.x, f = threadIdx.x;
    double denom = (double)(EPG + NUM_NODE) * (double)ED;
    float mean = (float)(g_esum[g] / denom);
    float var  = (float)(g_esq[g] / denom) - mean * mean;
    float istd = rsqrtf(var + EPSV);
    float s = istd * wle[f];
    float o = ble[f] - mean * s;
    g_se[g * ED + f] = s;
    g_oe[g * ED + f] = o;
    oesh[f] = o;
    __syncthreads();
    float acc = bg[f];
#pragma unroll 8
    for (int k = 0; k < ED; k++) acc += oesh[k] * Wg[k * ED + f];
    g_bgp[g * ED + f] = acc;
}

// GEMM D: z = (s_e ⊙ he) @ W_glob  (per-node; f32x2)
__global__ __launch_bounds__(256) void gemm_z_kernel(const float* __restrict__ Wg) {
    const int K = ED, NF = ED;
    __shared__ float As[2][8][SMP];
    __shared__ float Bs[2][8][SMP];
    int tid = threadIdx.x;
    int bm = blockIdx.x * 128;
    int ty = tid >> 4, tx = tid & 15;
    int lar = tid >> 1, lac = (tid & 1) << 2;
    int lbk = tid >> 5, lbn = (tid & 31) << 2;
    unsigned long long acc2[8][4] = {};
    int g = bm >> 11;

    float4 av = *(const float4*)(g_he + (size_t)(bm + lar) * K + lac);
    float4 sv = *(const float4*)(g_se + g * ED + lac);
    av.x *= sv.x; av.y *= sv.y; av.z *= sv.z; av.w *= sv.w;
    float4 bvw = *(const float4*)(Wg + (size_t)lbk * NF + lbn);
    As[0][lac + 0][lar] = av.x; As[0][lac + 1][lar] = av.y;
    As[0][lac + 2][lar] = av.z; As[0][lac + 3][lar] = av.w;
    *(float4*)&Bs[0][lbk][lbn] = bvw;

    const int T = K / 8;
    for (int it = 0; it < T; ++it) {
        if (it + 1 < T) {
            int k0 = (it + 1) * 8;
            av = *(const float4*)(g_he + (size_t)(bm + lar) * K + k0 + lac);
            sv = *(const float4*)(g_se + g * ED + k0 + lac);
            av.x *= sv.x; av.y *= sv.y; av.z *= sv.z; av.w *= sv.w;
            bvw = *(const float4*)(Wg + (size_t)(k0 + lbk) * NF + lbn);
        }
        __syncthreads();
        int cur = it & 1;
#pragma unroll
        for (int kk = 0; kk < 8; kk++) {
            float a[8];
            unsigned long long b2[4];
            FRAG_LOAD2(As, Bs, cur, kk, a, b2)
            FMA2_8x8(acc2, a, b2)
        }
        if (it + 1 < T) {
            int nxt = cur ^ 1;
            As[nxt][lac + 0][lar] = av.x; As[nxt][lac + 1][lar] = av.y;
            As[nxt][lac + 2][lar] = av.z; As[nxt][lac + 3][lar] = av.w;
            *(float4*)&Bs[nxt][lbk][lbn] = bvw;
        }
    }
#pragma unroll
    for (int i = 0; i < 8; i++) {
        int row = bm + ((i < 4) ? ty * 4 + i : 64 + ty * 4 + i - 4);
#pragma unroll
        for (int jh = 0; jh < 2; jh++) {
            int col = jh * 64 + tx * 4;
            uint32_t u0, u1, u2, u3;
            UNPK2(u0, u1, acc2[i][2 * jh + 0])
            UNPK2(u2, u3, acc2[i][2 * jh + 1])
            float4 o;
            o.x = __uint_as_float(u0); o.y = __uint_as_float(u1);
            o.z = __uint_as_float(u2); o.w = __uint_as_float(u3);
            *(float4*)(g_z + (size_t)row * NF + col) = o;
        }
    }
}

// per edge: write edge_attr, accumulate per-graph sum of relu((z_r+z_c)/2 + bg')
__global__ void edge_write_kernel(const int* __restrict__ rowi, const int* __restrict__ coli,
                                  float* __restrict__ edge_out) {
    __shared__ int sr[64], sc[64];
    int e0 = blockIdx.x * 64;
    int f = threadIdx.x;
    int g = (e0 < EO) ? (e0 >> 15) : ((e0 - EO) >> 11);
    if (f < 64) {
        int e = e0 + f;
        if (e < EO) { sr[f] = rowi[e]; sc[f] = coli[e]; }
        else        { sr[f] = e - EO; sc[f] = e - EO; }
    }
    __syncthreads();
    float s = g_se[g * ED + f], o = g_oe[g * ED + f], bgp = g_bgp[g * ED + f];
    float acc = 0.f;
#pragma unroll 4
    for (int q = 0; q < 64; q++) {
        int r = sr[q], c = sc[q];
        float hv = 0.5f * (g_he[(size_t)r * ED + f] + g_he[(size_t)c * ED + f]);
        edge_out[(size_t)(e0 + q) * ED + f] = s * hv + o;
        float zv = 0.5f * (g_z[(size_t)r * ED + f] + g_z[(size_t)c * ED + f]) + bgp;
        acc += fmaxf(zv, 0.f);
    }
    atomicAdd(&g_gsum[g * ED + f], acc);
}

// global pooling mean + LN over 128 features per graph
__global__ void global_kernel(const float* __restrict__ wlg, const float* __restrict__ blg,
                              float* __restrict__ u_out) {
    __shared__ float sm[32];
    int g = blockIdx.x, f = threadIdx.x;
    float p = g_gsum[g * ED + f] / (float)(EPG + NUM_NODE);
    float s1 = block_reduce(p, sm);
    float s2 = block_reduce(p * p, sm);
    float mean = s1 / (float)ED;
    float var  = s2 / (float)ED - mean * mean;
    u_out[g * ED + f] = (p - mean) * rsqrtf(var + EPSV) * wlg[f] + blg[f];
}

// ---------------- launch ----------------
extern "C" void kernel_launch(void* const* d_in, const int* in_sizes, int n_in,
                              void* d_out, int out_size) {
    (void)in_sizes; (void)n_in; (void)out_size;
    const float* x        = (const float*)d_in[0];
    const int*   atom_ids = (const int*)  d_in[1];
    const int*   aa_ids   = (const int*)  d_in[2];
    const int*   ei       = (const int*)  d_in[3];
    const float* W1 = (const float*)d_in[4];  const float* b1 = (const float*)d_in[5];
    const float* W2 = (const float*)d_in[6];  const float* b2 = (const float*)d_in[7];
    const float* W3 = (const float*)d_in[8];  const float* b3 = (const float*)d_in[9];
    const float* W4 = (const float*)d_in[10]; const float* b4 = (const float*)d_in[11];
    const float* Wd = (const float*)d_in[12]; const float* bd = (const float*)d_in[13];
    const float* atom_emb = (const float*)d_in[14];
    const float* aa_emb   = (const float*)d_in[15];
    const float* wlc = (const float*)d_in[16]; const float* blc = (const float*)d_in[17];
    const float* wln = (const float*)d_in[18]; const float* bln = (const float*)d_in[19];
    const float* We  = (const float*)d_in[20]; const float* be  = (const float*)d_in[21];
    const float* wle = (const float*)d_in[22]; const float* ble = (const float*)d_in[23];
    const float* Wg  = (const float*)d_in[24]; const float* bg  = (const float*)d_in[25];
    const float* wlg = (const float*)d_in[26]; const float* blg = (const float*)d_in[27];

    float* out      = (float*)d_out;
    float* h_out    = out;
    float* edge_out = out + (size_t)NN * ND;
    float* u_out    = edge_out + (size_t)ET * ED;

    const int* ei_row = ei;
    const int* ei_col = ei + EO;

    zero_stats_kernel<<<8, 256>>>();
    coord_stats_kernel<<<NB, 256>>>(x);
    node_mlp_kernel<<<NN / 256, 256>>>(x, W1, b1, W2, b2, W3, b3, wlc, blc);
    gemm_pre4_kernel<<<dim3(NN / 128, ND / 128), 256>>>(W4, b4);
    gemm_dense_kernel<<<dim3(NN / 128, ND / 128), 256>>>(Wd, bd, atom_ids, aa_ids, atom_emb, aa_emb);
    finalize_node_kernel<<<1, NB>>>();
    gemm_edge_kernel<<<NN / 128, 256>>>(We, be, wln, bln, h_out);
    edge_stats_kernel<<<ET / 256, 256>>>(ei_row, ei_col);
    edge_params_kernel<<<NB, ED>>>(wle, ble, Wg, bg);
    gemm_z_kernel<<<NN / 128, 256>>>(Wg);
    edge_write_kernel<<<ET / 64, ED>>>(ei_row, ei_col, edge_out);
    global_kernel<<<NB, ED>>>(wlg, blg, u_out);
}

// round 15
// speedup vs baseline: 1.1862x; 1.0236x over previous
#include <cuda_runtime.h>
#include <cstdint>

// ---------------- problem constants ----------------
#define NB 16          // graphs (batch)
#define NUM_NODE 2048
#define NN 32768       // total nodes
#define EO 524288      // original edges
#define EPG 32768      // edges per graph (original)
#define ET 557056      // edges + self loops
#define ND 768         // node dim
#define ED 128         // edge dim / glob dim
#define EPSV 1e-5f
#define SMP 132        // padded smem row stride (floats)

// ---------------- scratch (device globals; no allocation) ----------------
__device__ float  g_a192[192 * NN];   // K-major [192][NN]
__device__ float  g_a768[(size_t)NN * ND];
__device__ float  g_t[(size_t)NN * ND];
__device__ float  g_he[NN * ED];
__device__ float  g_z[NN * ED];
__device__ float  g_cmean[NB], g_cistd[NB];
__device__ double g_nsum[NB], g_nsq[NB];
__device__ float  g_nmean[NB], g_nistd[NB];
__device__ double g_esum[NB], g_esq[NB];
__device__ float  g_se[NB * ED], g_oe[NB * ED], g_bgp[NB * ED];
__device__ float  g_gsum[NB * ED];

// ---------------- helpers ----------------
__device__ __forceinline__ float block_reduce(float v, float* sm) {
#pragma unroll
    for (int o = 16; o; o >>= 1) v += __shfl_xor_sync(0xffffffffu, v, o);
    int lane = threadIdx.x & 31, w = threadIdx.x >> 5;
    if (lane == 0) sm[w] = v;
    __syncthreads();
    int nw = (blockDim.x + 31) >> 5;
    if (w == 0) {
        v = (lane < nw) ? sm[lane] : 0.f;
#pragma unroll
        for (int o = 16; o; o >>= 1) v += __shfl_xor_sync(0xffffffffu, v, o);
        if (lane == 0) sm[0] = v;
    }
    __syncthreads();
    v = sm[0];
    __syncthreads();
    return v;
}

// ---------------- packed f32x2 inner product (FFMA2) with frag double-buffer ----
// FRAG_LD: load fragments for step kk into buffer fa/fb (subarray expressions)
#define FRAG_LD(As, Bs, cur, kk, fa, fb)                                  \
    *(float4*)&(fa)[0] = *(float4*)&As[cur][kk][ty * 4];                  \
    *(float4*)&(fa)[4] = *(float4*)&As[cur][kk][64 + ty * 4];             \
    *(ulonglong2*)&(fb)[0] = *(const ulonglong2*)&Bs[cur][kk][tx * 4];    \
    *(ulonglong2*)&(fb)[2] = *(const ulonglong2*)&Bs[cur][kk][64 + tx * 4];

#define FMA2_STEP(acc2, fa, fb)                                           \
    _Pragma("unroll")                                                     \
    for (int i = 0; i < 8; i++) {                                         \
        unsigned long long aa;                                            \
        asm("mov.b64 %0, {%1, %1};" : "=l"(aa) : "r"(__float_as_uint((fa)[i]))); \
        _Pragma("unroll")                                                 \
        for (int q = 0; q < 4; q++)                                       \
            asm("fma.rn.f32x2 %0, %1, %2, %0;"                            \
                : "+l"(acc2[i][q]) : "l"(aa), "l"((fb)[q]));              \
    }

// inner loop over 8 k-steps with 2-deep fragment pipeline
#define KBLOCK_PIPE(As, Bs, cur)                                          \
    {                                                                     \
        float fa[2][8];                                                   \
        unsigned long long fb[2][4];                                      \
        FRAG_LD(As, Bs, cur, 0, fa[0], fb[0])                             \
        _Pragma("unroll")                                                 \
        for (int kk = 0; kk < 8; kk++) {                                  \
            if (kk < 7) { FRAG_LD(As, Bs, cur, (kk + 1), fa[(kk + 1) & 1], fb[(kk + 1) & 1]) } \
            FMA2_STEP(acc2, fa[kk & 1], fb[kk & 1])                       \
        }                                                                 \
    }

#define UNPK2(lo, hi, c) \
    asm("mov.b64 {%0, %1}, %2;" : "=r"(lo), "=r"(hi) : "l"(c));

// ---------------- kernels ----------------
__global__ void zero_stats_kernel() {
    int t = blockIdx.x * blockDim.x + threadIdx.x;
    if (t < NB) { g_nsum[t] = 0.0; g_nsq[t] = 0.0; g_esum[t] = 0.0; g_esq[t] = 0.0; }
    if (t < NB * ED) g_gsum[t] = 0.f;
}

__global__ void coord_stats_kernel(const float* __restrict__ x) {
    __shared__ float sm[32];
    int g = blockIdx.x;
    const float* xg = x + (size_t)g * NUM_NODE * 3;
    float s = 0.f, ss = 0.f;
    for (int i = threadIdx.x; i < NUM_NODE * 3; i += blockDim.x) {
        float v = xg[i]; s += v; ss += v * v;
    }
    s  = block_reduce(s, sm);
    ss = block_reduce(ss, sm);
    if (threadIdx.x == 0) {
        float mean = s / (float)(NUM_NODE * 3);
        float var  = ss / (float)(NUM_NODE * 3) - mean * mean;
        g_cmean[g] = mean;
        g_cistd[g] = rsqrtf(var + EPSV);
    }
}

// coord LN + MLP 3->12->48->192, output K-major a192[j][node]
__global__ __launch_bounds__(256) void node_mlp_kernel(
    const float* __restrict__ x,
    const float* __restrict__ W1, const float* __restrict__ b1,
    const float* __restrict__ W2, const float* __restrict__ b2,
    const float* __restrict__ W3, const float* __restrict__ b3,
    const float* __restrict__ wlc, const float* __restrict__ blc) {
    __shared__ float W1s[36], b1s[12], W2s[576], b2s[48], W3s[9216], b3s[192], wlcs[3], blcs[3];
    int tid = threadIdx.x;
    for (int i = tid; i < 36;   i += 256) W1s[i] = W1[i];
    for (int i = tid; i < 12;   i += 256) b1s[i] = b1[i];
    for (int i = tid; i < 576;  i += 256) W2s[i] = W2[i];
    for (int i = tid; i < 48;   i += 256) b2s[i] = b2[i];
    for (int i = tid; i < 9216; i += 256) W3s[i] = W3[i];
    for (int i = tid; i < 192;  i += 256) b3s[i] = b3[i];
    if (tid < 3) { wlcs[tid] = wlc[tid]; blcs[tid] = blc[tid]; }
    __syncthreads();

    int node = blockIdx.x * 256 + tid;
    int g = node >> 11;
    float mean = g_cmean[g], istd = g_cistd[g];
    float h0[3];
#pragma unroll
    for (int c = 0; c < 3; c++)
        h0[c] = (x[node * 3 + c] - mean) * istd * wlcs[c] + blcs[c];

    float v12[12];
#pragma unroll
    for (int j = 0; j < 12; j++) {
        float a = b1s[j];
#pragma unroll
        for (int c = 0; c < 3; c++) a += h0[c] * W1s[c * 12 + j];
        v12[j] = fmaxf(a, 0.f);
    }
    float v48[48];
#pragma unroll
    for (int j = 0; j < 48; j++) {
        float a = b2s[j];
#pragma unroll
        for (int k = 0; k < 12; k++) a += v12[k] * W2s[k * 48 + j];
        v48[j] = fmaxf(a, 0.f);
    }
    for (int j = 0; j < 192; j++) {
        float a = b3s[j];
#pragma unroll
        for (int k = 0; k < 48; k++) a += v48[k] * W3s[k * 192 + j];
        g_a192[(size_t)j * NN + node] = fmaxf(a, 0.f);   // coalesced across tid
    }
}

// GEMM A: a768 = relu(a192 @ W_pre4 + b). A is K-major [192][NN]. f32x2 + frag pipe.
__global__ __launch_bounds__(256) void gemm_pre4_kernel(
    const float* __restrict__ W, const float* __restrict__ bias) {
    const int M = NN, K = 192, NF = ND;
    __shared__ float As[2][8][SMP];
    __shared__ float Bs[2][8][SMP];
    int tid = threadIdx.x;
    int bm = blockIdx.x * 128, bn = blockIdx.y * 128;
    int ty = tid >> 4, tx = tid & 15;
    int lk = tid >> 5, lm = (tid & 31) << 2;
    unsigned long long acc2[8][4] = {};

    float4 av = *(const float4*)(g_a192 + (size_t)lk * M + bm + lm);
    float4 bv = *(const float4*)(W + (size_t)lk * NF + bn + lm);
    *(float4*)&As[0][lk][lm] = av;
    *(float4*)&Bs[0][lk][lm] = bv;

    const int T = K / 8;
    for (int it = 0; it < T; ++it) {
        if (it + 1 < T) {
            int k0 = (it + 1) * 8;
            av = *(const float4*)(g_a192 + (size_t)(k0 + lk) * M + bm + lm);
            bv = *(const float4*)(W + (size_t)(k0 + lk) * NF + bn + lm);
        }
        __syncthreads();
        int cur = it & 1;
        KBLOCK_PIPE(As, Bs, cur)
        if (it + 1 < T) {
            int nxt = cur ^ 1;
            *(float4*)&As[nxt][lk][lm] = av;
            *(float4*)&Bs[nxt][lk][lm] = bv;
        }
    }
#pragma unroll
    for (int i = 0; i < 8; i++) {
        int row = bm + ((i < 4) ? ty * 4 + i : 64 + ty * 4 + i - 4);
#pragma unroll
        for (int jh = 0; jh < 2; jh++) {
            int col = bn + jh * 64 + tx * 4;
            uint32_t u0, u1, u2, u3;
            UNPK2(u0, u1, acc2[i][2 * jh + 0])
            UNPK2(u2, u3, acc2[i][2 * jh + 1])
            float4 o;
            o.x = fmaxf(__uint_as_float(u0) + bias[col + 0], 0.f);
            o.y = fmaxf(__uint_as_float(u1) + bias[col + 1], 0.f);
            o.z = fmaxf(__uint_as_float(u2) + bias[col + 2], 0.f);
            o.w = fmaxf(__uint_as_float(u3) + bias[col + 3], 0.f);
            *(float4*)(g_a768 + (size_t)row * NF + col) = o;
        }
    }
}

// GEMM B: t = relu(a768 @ W_dense + b) + atom_emb + aa_emb; fused per-graph sum/sumsq
__global__ __launch_bounds__(256) void gemm_dense_kernel(
    const float* __restrict__ W, const float* __restrict__ bias,
    const int* __restrict__ atom_ids, const int* __restrict__ aa_ids,
    const float* __restrict__ atom_emb, const float* __restrict__ aa_emb) {
    const int K = ND, NF = ND;
    __shared__ float As[2][8][SMP];
    __shared__ float Bs[2][8][SMP];
    __shared__ float sm[32];
    int tid = threadIdx.x;
    int bm = blockIdx.x * 128, bn = blockIdx.y * 128;
    int ty = tid >> 4, tx = tid & 15;
    int lar = tid >> 1, lac = (tid & 1) << 2;
    int lbk = tid >> 5, lbn = (tid & 31) << 2;
    unsigned long long acc2[8][4] = {};

    float4 av = *(const float4*)(g_a768 + (size_t)(bm + lar) * K + lac);
    float4 bv = *(const float4*)(W + (size_t)lbk * NF + bn + lbn);
    As[0][lac + 0][lar] = av.x; As[0][lac + 1][lar] = av.y;
    As[0][lac + 2][lar] = av.z; As[0][lac + 3][lar] = av.w;
    *(float4*)&Bs[0][lbk][lbn] = bv;

    const int T = K / 8;
    for (int it = 0; it < T; ++it) {
        if (it + 1 < T) {
            int k0 = (it + 1) * 8;
            av = *(const float4*)(g_a768 + (size_t)(bm + lar) * K + k0 + lac);
            bv = *(const float4*)(W + (size_t)(k0 + lbk) * NF + bn + lbn);
        }
        __syncthreads();
        int cur = it & 1;
        KBLOCK_PIPE(As, Bs, cur)
        if (it + 1 < T) {
            int nxt = cur ^ 1;
            As[nxt][lac + 0][lar] = av.x; As[nxt][lac + 1][lar] = av.y;
            As[nxt][lac + 2][lar] = av.z; As[nxt][lac + 3][lar] = av.w;
            *(float4*)&Bs[nxt][lbk][lbn] = bv;
        }
    }
    float ls = 0.f, lss = 0.f;
    int g = bm >> 11;  // 128-row tile never straddles a graph
#pragma unroll
    for (int i = 0; i < 8; i++) {
        int row = bm + ((i < 4) ? ty * 4 + i : 64 + ty * 4 + i - 4);
        int at = atom_ids[row], aa = aa_ids[row];
#pragma unroll
        for (int jh = 0; jh < 2; jh++) {
            int col = bn + jh * 64 + tx * 4;
            uint32_t u0, u1, u2, u3;
            UNPK2(u0, u1, acc2[i][2 * jh + 0])
            UNPK2(u2, u3, acc2[i][2 * jh + 1])
            float4 bb = *(const float4*)(bias + col);
            float4 ea = *(const float4*)(atom_emb + (size_t)at * ND + col);
            float4 eb = *(const float4*)(aa_emb + (size_t)aa * ND + col);
            float4 o;
            o.x = fmaxf(__uint_as_float(u0) + bb.x, 0.f) + ea.x + eb.x;
            o.y = fmaxf(__uint_as_float(u1) + bb.y, 0.f) + ea.y + eb.y;
            o.z = fmaxf(__uint_as_float(u2) + bb.z, 0.f) + ea.z + eb.z;
            o.w = fmaxf(__uint_as_float(u3) + bb.w, 0.f) + ea.w + eb.w;
            ls  += o.x + o.y + o.z + o.w;
            lss += o.x * o.x + o.y * o.y + o.z * o.z + o.w * o.w;
            *(float4*)(g_t + (size_t)row * NF + col) = o;
        }
    }
    ls  = block_reduce(ls, sm);
    lss = block_reduce(lss, sm);
    if (tid == 0) {
        atomicAdd(&g_nsum[g], (double)ls);
        atomicAdd(&g_nsq[g], (double)lss);
    }
}

__global__ void finalize_node_kernel() {
    int g = threadIdx.x;
    if (g >= NB) return;
    double denom = (double)NUM_NODE * (double)ND;
    float mean = (float)(g_nsum[g] / denom);
    float var  = (float)(g_nsq[g] / denom) - mean * mean;
    g_nmean[g] = mean;
    g_nistd[g] = rsqrtf(var + EPSV);
}

// GEMM C: h = LN(t) (written to output), he = relu(h @ W_edge + b_edge). NF=128.
__global__ __launch_bounds__(256) void gemm_edge_kernel(
    const float* __restrict__ W, const float* __restrict__ bias,
    const float* __restrict__ wln, const float* __restrict__ bln,
    float* __restrict__ h_out) {
    const int K = ND, NF = ED;
    __shared__ float As[2][8][SMP];
    __shared__ float Bs[2][8][SMP];
    int tid = threadIdx.x;
    int bm = blockIdx.x * 128;
    int ty = tid >> 4, tx = tid & 15;
    int lar = tid >> 1, lac = (tid & 1) << 2;
    int lbk = tid >> 5, lbn = (tid & 31) << 2;
    unsigned long long acc2[8][4] = {};
    int g = bm >> 11;
    float mean = g_nmean[g], istd = g_nistd[g];

    float4 av = *(const float4*)(g_t + (size_t)(bm + lar) * K + lac);
    float4 wv = *(const float4*)(wln + lac);
    float4 bv2 = *(const float4*)(bln + lac);
    float4 hv;
    hv.x = (av.x - mean) * istd * wv.x + bv2.x;
    hv.y = (av.y - mean) * istd * wv.y + bv2.y;
    hv.z = (av.z - mean) * istd * wv.z + bv2.z;
    hv.w = (av.w - mean) * istd * wv.w + bv2.w;
    *(float4*)(h_out + (size_t)(bm + lar) * ND + lac) = hv;
    float4 bvw = *(const float4*)(W + (size_t)lbk * NF + lbn);
    As[0][lac + 0][lar] = hv.x; As[0][lac + 1][lar] = hv.y;
    As[0][lac + 2][lar] = hv.z; As[0][lac + 3][lar] = hv.w;
    *(float4*)&Bs[0][lbk][lbn] = bvw;

    const int T = K / 8;
    for (int it = 0; it < T; ++it) {
        if (it + 1 < T) {
            int k0 = (it + 1) * 8;
            av = *(const float4*)(g_t + (size_t)(bm + lar) * K + k0 + lac);
            wv = *(const float4*)(wln + k0 + lac);
            bv2 = *(const float4*)(bln + k0 + lac);
            hv.x = (av.x - mean) * istd * wv.x + bv2.x;
            hv.y = (av.y - mean) * istd * wv.y + bv2.y;
            hv.z = (av.z - mean) * istd * wv.z + bv2.z;
            hv.w = (av.w - mean) * istd * wv.w + bv2.w;
            *(float4*)(h_out + (size_t)(bm + lar) * ND + k0 + lac) = hv;
            bvw = *(const float4*)(W + (size_t)(k0 + lbk) * NF + lbn);
        }
        __syncthreads();
        int cur = it & 1;
        KBLOCK_PIPE(As, Bs, cur)
        if (it + 1 < T) {
            int nxt = cur ^ 1;
            As[nxt][lac + 0][lar] = hv.x; As[nxt][lac + 1][lar] = hv.y;
            As[nxt][lac + 2][lar] = hv.z; As[nxt][lac + 3][lar] = hv.w;
            *(float4*)&Bs[nxt][lbk][lbn] = bvw;
        }
    }
#pragma unroll
    for (int i = 0; i < 8; i++) {
        int row = bm + ((i < 4) ? ty * 4 + i : 64 + ty * 4 + i - 4);
#pragma unroll
        for (int jh = 0; jh < 2; jh++) {
            int col = jh * 64 + tx * 4;
            uint32_t u0, u1, u2, u3;
            UNPK2(u0, u1, acc2[i][2 * jh + 0])
            UNPK2(u2, u3, acc2[i][2 * jh + 1])
            float4 o;
            o.x = fmaxf(__uint_as_float(u0) + bias[col + 0], 0.f);
            o.y = fmaxf(__uint_as_float(u1) + bias[col + 1], 0.f);
            o.z = fmaxf(__uint_as_float(u2) + bias[col + 2], 0.f);
            o.w = fmaxf(__uint_as_float(u3) + bias[col + 3], 0.f);
            *(float4*)(g_he + (size_t)row * NF + col) = o;
        }
    }
}

// per-graph edge sum/sumsq over e = 0.5*(he[row]+he[col])
__global__ void edge_stats_kernel(const int* __restrict__ rowi, const int* __restrict__ coli) {
    __shared__ float sm[32];
    int e = blockIdx.x * 256 + threadIdx.x;
    int r, c, g;
    if (e < EO) { r = rowi[e]; c = coli[e]; g = e >> 15; }
    else        { int i = e - EO; r = i; c = i; g = i >> 11; }
    const float4* hr = (const float4*)(g_he + (size_t)r * ED);
    const float4* hc = (const float4*)(g_he + (size_t)c * ED);
    float s = 0.f, ss = 0.f;
#pragma unroll 8
    for (int q = 0; q < 32; q++) {
        float4 a = hr[q], b = hc[q];
        float v;
        v = 0.5f * (a.x + b.x); s += v; ss += v * v;
        v = 0.5f * (a.y + b.y); s += v; ss += v * v;
        v = 0.5f * (a.z + b.z); s += v; ss += v * v;
        v = 0.5f * (a.w + b.w); s += v; ss += v * v;
    }
    s  = block_reduce(s, sm);
    ss = block_reduce(ss, sm);
    if (threadIdx.x == 0) {
        atomicAdd(&g_esum[g], (double)s);
        atomicAdd(&g_esq[g], (double)ss);
    }
}

// per-graph edge-LN affine params + folded global bias bg' = o_e @ W_glob + b_glob
__global__ void edge_params_kernel(
    const float* __restrict__ wle, const float* __restrict__ ble,
    const float* __restrict__ Wg, const float* __restrict__ bg) {
    __shared__ float oesh[ED];
    int g = blockIdx.x, f = threadIdx.x;
    double denom = (double)(EPG + NUM_NODE) * (double)ED;
    float mean = (float)(g_esum[g] / denom);
    float var  = (float)(g_esq[g] / denom) - mean * mean;
    float istd = rsqrtf(var + EPSV);
    float s = istd * wle[f];
    float o = ble[f] - mean * s;
    g_se[g * ED + f] = s;
    g_oe[g * ED + f] = o;
    oesh[f] = o;
    __syncthreads();
    float acc = bg[f];
#pragma unroll 8
    for (int k = 0; k < ED; k++) acc += oesh[k] * Wg[k * ED + f];
    g_bgp[g * ED + f] = acc;
}

// GEMM D: z = (s_e ⊙ he) @ W_glob  (per-node; f32x2 + frag pipe)
__global__ __launch_bounds__(256) void gemm_z_kernel(const float* __restrict__ Wg) {
    const int K = ED, NF = ED;
    __shared__ float As[2][8][SMP];
    __shared__ float Bs[2][8][SMP];
    int tid = threadIdx.x;
    int bm = blockIdx.x * 128;
    int ty = tid >> 4, tx = tid & 15;
    int lar = tid >> 1, lac = (tid & 1) << 2;
    int lbk = tid >> 5, lbn = (tid & 31) << 2;
    unsigned long long acc2[8][4] = {};
    int g = bm >> 11;

    float4 av = *(const float4*)(g_he + (size_t)(bm + lar) * K + lac);
    float4 sv = *(const float4*)(g_se + g * ED + lac);
    av.x *= sv.x; av.y *= sv.y; av.z *= sv.z; av.w *= sv.w;
    float4 bvw = *(const float4*)(Wg + (size_t)lbk * NF + lbn);
    As[0][lac + 0][lar] = av.x; As[0][lac + 1][lar] = av.y;
    As[0][lac + 2][lar] = av.z; As[0][lac + 3][lar] = av.w;
    *(float4*)&Bs[0][lbk][lbn] = bvw;

    const int T = K / 8;
    for (int it = 0; it < T; ++it) {
        if (it + 1 < T) {
            int k0 = (it + 1) * 8;
            av = *(const float4*)(g_he + (size_t)(bm + lar) * K + k0 + lac);
            sv = *(const float4*)(g_se + g * ED + k0 + lac);
            av.x *= sv.x; av.y *= sv.y; av.z *= sv.z; av.w *= sv.w;
            bvw = *(const float4*)(Wg + (size_t)(k0 + lbk) * NF + lbn);
        }
        __syncthreads();
        int cur = it & 1;
        KBLOCK_PIPE(As, Bs, cur)
        if (it + 1 < T) {
            int nxt = cur ^ 1;
            As[nxt][lac + 0][lar] = av.x; As[nxt][lac + 1][lar] = av.y;
            As[nxt][lac + 2][lar] = av.z; As[nxt][lac + 3][lar] = av.w;
            *(float4*)&Bs[nxt][lbk][lbn] = bvw;
        }
    }
#pragma unroll
    for (int i = 0; i < 8; i++) {
        int row = bm + ((i < 4) ? ty * 4 + i : 64 + ty * 4 + i - 4);
#pragma unroll
        for (int jh = 0; jh < 2; jh++) {
            int col = jh * 64 + tx * 4;
            uint32_t u0, u1, u2, u3;
            UNPK2(u0, u1, acc2[i][2 * jh + 0])
            UNPK2(u2, u3, acc2[i][2 * jh + 1])
            float4 o;
            o.x = __uint_as_float(u0); o.y = __uint_as_float(u1);
            o.z = __uint_as_float(u2); o.w = __uint_as_float(u3);
            *(float4*)(g_z + (size_t)row * NF + col) = o;
        }
    }
}

// per edge: write edge_attr, accumulate per-graph sum of relu((z_r+z_c)/2 + bg')
__global__ void edge_write_kernel(const int* __restrict__ rowi, const int* __restrict__ coli,
                                  float* __restrict__ edge_out) {
    __shared__ int sr[64], sc[64];
    int e0 = blockIdx.x * 64;
    int f = threadIdx.x;
    int g = (e0 < EO) ? (e0 >> 15) : ((e0 - EO) >> 11);
    if (f < 64) {
        int e = e0 + f;
        if (e < EO) { sr[f] = rowi[e]; sc[f] = coli[e]; }
        else        { sr[f] = e - EO; sc[f] = e - EO; }
    }
    __syncthreads();
    float s = g_se[g * ED + f], o = g_oe[g * ED + f], bgp = g_bgp[g * ED + f];
    float acc = 0.f;
#pragma unroll 4
    for (int q = 0; q < 64; q++) {
        int r = sr[q], c = sc[q];
        float hv = 0.5f * (g_he[(size_t)r * ED + f] + g_he[(size_t)c * ED + f]);
        edge_out[(size_t)(e0 + q) * ED + f] = s * hv + o;
        float zv = 0.5f * (g_z[(size_t)r * ED + f] + g_z[(size_t)c * ED + f]) + bgp;
        acc += fmaxf(zv, 0.f);
    }
    atomicAdd(&g_gsum[g * ED + f], acc);
}

// global pooling mean + LN over 128 features per graph
__global__ void global_kernel(const float* __restrict__ wlg, const float* __restrict__ blg,
                              float* __restrict__ u_out) {
    __shared__ float sm[32];
    int g = blockIdx.x, f = threadIdx.x;
    float p = g_gsum[g * ED + f] / (float)(EPG + NUM_NODE);
    float s1 = block_reduce(p, sm);
    float s2 = block_reduce(p * p, sm);
    float mean = s1 / (float)ED;
    float var  = s2 / (float)ED - mean * mean;
    u_out[g * ED + f] = (p - mean) * rsqrtf(var + EPSV) * wlg[f] + blg[f];
}

// ---------------- launch ----------------
extern "C" void kernel_launch(void* const* d_in, const int* in_sizes, int n_in,
                              void* d_out, int out_size) {
    (void)in_sizes; (void)n_in; (void)out_size;
    const float* x        = (const float*)d_in[0];
    const int*   atom_ids = (const int*)  d_in[1];
    const int*   aa_ids   = (const int*)  d_in[2];
    const int*   ei       = (const int*)  d_in[3];
    const float* W1 = (const float*)d_in[4];  const float* b1 = (const float*)d_in[5];
    const float* W2 = (const float*)d_in[6];  const float* b2 = (const float*)d_in[7];
    const float* W3 = (const float*)d_in[8];  const float* b3 = (const float*)d_in[9];
    const float* W4 = (const float*)d_in[10]; const float* b4 = (const float*)d_in[11];
    const float* Wd = (const float*)d_in[12]; const float* bd = (const float*)d_in[13];
    const float* atom_emb = (const float*)d_in[14];
    const float* aa_emb   = (const float*)d_in[15];
    const float* wlc = (const float*)d_in[16]; const float* blc = (const float*)d_in[17];
    const float* wln = (const float*)d_in[18]; const float* bln = (const float*)d_in[19];
    const float* We  = (const float*)d_in[20]; const float* be  = (const float*)d_in[21];
    const float* wle = (const float*)d_in[22]; const float* ble = (const float*)d_in[23];
    const float* Wg  = (const float*)d_in[24]; const float* bg  = (const float*)d_in[25];
    const float* wlg = (const float*)d_in[26]; const float* blg = (const float*)d_in[27];

    float* out      = (float*)d_out;
    float* h_out    = out;
    float* edge_out = out + (size_t)NN * ND;
    float* u_out    = edge_out + (size_t)ET * ED;

    const int* ei_row = ei;
    const int* ei_col = ei + EO;

    zero_stats_kernel<<<8, 256>>>();
    coord_stats_kernel<<<NB, 256>>>(x);
    node_mlp_kernel<<<NN / 256, 256>>>(x, W1, b1, W2, b2, W3, b3, wlc, blc);
    gemm_pre4_kernel<<<dim3(NN / 128, ND / 128), 256>>>(W4, b4);
    gemm_dense_kernel<<<dim3(NN / 128, ND / 128), 256>>>(Wd, bd, atom_ids, aa_ids, atom_emb, aa_emb);
    finalize_node_kernel<<<1, NB>>>();
    gemm_edge_kernel<<<NN / 128, 256>>>(We, be, wln, bln, h_out);
    edge_stats_kernel<<<ET / 256, 256>>>(ei_row, ei_col);
    edge_params_kernel<<<NB, ED>>>(wle, ble, Wg, bg);
    gemm_z_kernel<<<NN / 128, 256>>>(Wg);
    edge_write_kernel<<<ET / 64, ED>>>(ei_row, ei_col, edge_out);
    global_kernel<<<NB, ED>>>(wlg, blg, u_out);
}